// round 9
// baseline (speedup 1.0000x reference)
#include <cuda_runtime.h>
#include <math.h>
#include <stdint.h>

// Problem constants
#define BB   8
#define CC   256
#define LL   1024          // H*W
#define DIN  512           // d_inner
#define DST  16            // d_state
#define RANK 16
#define HID  1024
#define MM   (BB*LL)       // 8192 tokens

// ---------------- scratch (device globals; no allocation APIs) -------------
__device__ float g_xt [MM*CC];     // x transposed (B,L,C) == residual 1
__device__ float g_xn [MM*CC];     // LN1 out
__device__ float g_xz [MM*2*DIN];  // xn @ W_in
__device__ float g_xm [MM*DIN];    // conv+silu out
__device__ float g_dbl[MM*48];     // xm @ W_x  (dt_raw | B | C)
__device__ float g_dt [MM*DIN];    // softplus(dt_raw @ W_dt + b_dt)
__device__ float g_yg [MM*DIN];    // gated scan output
__device__ float g_x2 [MM*CC];     // mamba out + res (residual 2)
__device__ float g_xn2[MM*CC];     // LN2 out
__device__ float g_h1 [MM*HID];    // gelu(xn2@W1+b1)
__device__ float g_x3 [MM*CC];     // final (B,L,C) before transpose

// ---------------- batched 2D transpose: (b,R,C) -> (b,C,R) -----------------
__global__ void transpose_k(const float* __restrict__ in, float* __restrict__ out,
                            int R, int Cc) {
    __shared__ float t[32][33];
    int b  = blockIdx.z;
    int r0 = blockIdx.y * 32, c0 = blockIdx.x * 32;
    const float* ib = in  + (size_t)b * R * Cc;
    float*       ob = out + (size_t)b * R * Cc;
#pragma unroll
    for (int i = 0; i < 32; i += 8)
        t[threadIdx.y + i][threadIdx.x] = ib[(r0 + threadIdx.y + i) * Cc + c0 + threadIdx.x];
    __syncthreads();
#pragma unroll
    for (int i = 0; i < 32; i += 8)
        ob[(c0 + threadIdx.y + i) * R + r0 + threadIdx.x] = t[threadIdx.x][threadIdx.y + i];
}

// -------- fused transpose (B,C,L)->(B,L,C) + LayerNorm over C --------------
__global__ __launch_bounds__(256)
void trln_k(const float* __restrict__ in, float* __restrict__ xt,
            float* __restrict__ xn, const float* __restrict__ g,
            const float* __restrict__ bt) {
    __shared__ float t[CC][33];
    __shared__ float ps[8][32], psq[8][32];
    __shared__ float mu[32], rs[32];
    int tx = threadIdx.x, ty = threadIdx.y;   // (32, 8)
    int l0 = blockIdx.x * 32;
    int b  = blockIdx.y;
    const float* ib = in + (size_t)b * CC * LL;

#pragma unroll
    for (int c = ty; c < CC; c += 8)
        t[c][tx] = ib[(size_t)c * LL + l0 + tx];
    __syncthreads();

    float s = 0.f, sq = 0.f;
#pragma unroll
    for (int i = 0; i < 32; i++) {
        float v = t[ty * 32 + i][tx];
        s += v; sq = fmaf(v, v, sq);
    }
    ps[ty][tx] = s; psq[ty][tx] = sq;
    __syncthreads();
    if (ty == 0) {
        float tot = 0.f, totq = 0.f;
#pragma unroll
        for (int i = 0; i < 8; i++) { tot += ps[i][tx]; totq += psq[i][tx]; }
        float m = tot * (1.0f / CC);
        float var = totq * (1.0f / CC) - m * m;
        mu[tx] = m; rs[tx] = rsqrtf(var + 1e-5f);
    }
    __syncthreads();

#pragma unroll
    for (int jj = ty; jj < 32; jj += 8) {
        float m = mu[jj], r = rs[jj];
        size_t base = ((size_t)b * LL + l0 + jj) * CC;
#pragma unroll
        for (int cc = tx; cc < CC; cc += 32) {
            float v = t[cc][jj];
            xt[base + cc] = v;
            xn[base + cc] = (v - m) * r * g[cc] + bt[cc];
        }
    }
}

// ---------------- layernorm over C=256, one block per token (LN2) ----------
__global__ void layernorm_k(const float* __restrict__ in, float* __restrict__ out,
                            const float* __restrict__ g, const float* __restrict__ bt) {
    int row = blockIdx.x;
    int tid = threadIdx.x;          // 256
    float v = in[row * CC + tid];
    float s = v, sq = v * v;
#pragma unroll
    for (int o = 16; o; o >>= 1) {
        s  += __shfl_xor_sync(0xffffffffu, s,  o);
        sq += __shfl_xor_sync(0xffffffffu, sq, o);
    }
    __shared__ float ss[8], ssq[8];
    int w = tid >> 5;
    if ((tid & 31) == 0) { ss[w] = s; ssq[w] = sq; }
    __syncthreads();
    float tot = 0.f, totq = 0.f;
#pragma unroll
    for (int i = 0; i < 8; i++) { tot += ss[i]; totq += ssq[i]; }
    float mu  = tot * (1.0f / CC);
    float var = totq * (1.0f / CC) - mu * mu;
    out[row * CC + tid] = (v - mu) * rsqrtf(var + 1e-5f) * g[tid] + bt[tid];
}

// ---------------- tf32 tensor-core GEMM (R2 version, measured-good) --------
__device__ __forceinline__ uint32_t f2tf32(float x) {
    uint32_t r;
    asm("cvt.rna.tf32.f32 %0, %1;" : "=r"(r) : "f"(x));
    return r;
}

__device__ __forceinline__ void mma_tf32(float* c, const uint32_t* a,
                                         uint32_t b0, uint32_t b1) {
    asm volatile(
        "mma.sync.aligned.m16n8k8.row.col.f32.tf32.tf32.f32 "
        "{%0,%1,%2,%3}, {%4,%5,%6,%7}, {%8,%9}, {%0,%1,%2,%3};"
        : "+f"(c[0]), "+f"(c[1]), "+f"(c[2]), "+f"(c[3])
        : "r"(a[0]), "r"(a[1]), "r"(a[2]), "r"(a[3]), "r"(b0), "r"(b1));
}

template<int EPI>
__global__ __launch_bounds__(256, 2)
void tf32gemm_k(const float* __restrict__ A, const float* __restrict__ Bm,
                float* __restrict__ Cout, int M, int N, int K,
                const float* __restrict__ bias, const float* __restrict__ res) {
    __shared__ uint32_t As[32][132];   // [k][m], padded
    __shared__ uint32_t Bs[32][132];   // [k][n], padded
    int tid  = threadIdx.x;
    int lane = tid & 31, warp = tid >> 5;
    int warpM = warp >> 1, warpN = warp & 1;     // 4 x 2 warps
    int bm = blockIdx.y * 128, bn = blockIdx.x * 128;
    int row4 = lane >> 2, kq = lane & 3;

    float acc[2][8][4];
#pragma unroll
    for (int i = 0; i < 2; i++)
#pragma unroll
        for (int j = 0; j < 8; j++)
#pragma unroll
            for (int q = 0; q < 4; q++) acc[i][j][q] = 0.f;

    for (int k0 = 0; k0 < K; k0 += 32) {
        // load A tile (128 rows x 32 k) -> As[k][m]
#pragma unroll
        for (int q = 0; q < 4; q++) {
            int idx = tid + 256 * q;
            int r = idx >> 3, c = (idx & 7) << 2;
            float4 v = *(const float4*)(A + (size_t)(bm + r) * K + k0 + c);
            As[c + 0][r] = f2tf32(v.x);
            As[c + 1][r] = f2tf32(v.y);
            As[c + 2][r] = f2tf32(v.z);
            As[c + 3][r] = f2tf32(v.w);
        }
        // load B tile (32 k x 128 n) -> Bs[k][n]
#pragma unroll
        for (int q = 0; q < 4; q++) {
            int idx = tid + 256 * q;
            int kk = idx >> 5, n = (idx & 31) << 2;
            float4 v = *(const float4*)(Bm + (size_t)(k0 + kk) * N + bn + n);
            Bs[kk][n + 0] = f2tf32(v.x);
            Bs[kk][n + 1] = f2tf32(v.y);
            Bs[kk][n + 2] = f2tf32(v.z);
            Bs[kk][n + 3] = f2tf32(v.w);
        }
        __syncthreads();
#pragma unroll
        for (int ks = 0; ks < 32; ks += 8) {
            uint32_t af[2][4];
#pragma unroll
            for (int mi = 0; mi < 2; mi++) {
                int m0 = warpM * 32 + mi * 16;
                af[mi][0] = As[ks + kq][m0 + row4];
                af[mi][1] = As[ks + kq][m0 + 8 + row4];
                af[mi][2] = As[ks + 4 + kq][m0 + row4];
                af[mi][3] = As[ks + 4 + kq][m0 + 8 + row4];
            }
#pragma unroll
            for (int ni = 0; ni < 8; ni++) {
                int n0 = warpN * 64 + ni * 8;
                uint32_t b0 = Bs[ks + kq][n0 + row4];
                uint32_t b1 = Bs[ks + 4 + kq][n0 + row4];
                mma_tf32(acc[0][ni], af[0], b0, b1);
                mma_tf32(acc[1][ni], af[1], b0, b1);
            }
        }
        __syncthreads();
    }

    // epilogue
#pragma unroll
    for (int mi = 0; mi < 2; mi++) {
        int r0 = bm + warpM * 32 + mi * 16 + row4;
#pragma unroll
        for (int ni = 0; ni < 8; ni++) {
            int col = bn + warpN * 64 + ni * 8 + kq * 2;
#pragma unroll
            for (int half = 0; half < 2; half++) {
                int row = r0 + half * 8;
                float v0 = acc[mi][ni][half * 2 + 0];
                float v1 = acc[mi][ni][half * 2 + 1];
                if (EPI == 1) {
                    v0 += res[(size_t)row * N + col];
                    v1 += res[(size_t)row * N + col + 1];
                }
                if (EPI == 2) {
                    v0 += bias[col];
                    v1 += bias[col + 1];
                    v0 = 0.5f * v0 * (1.0f + erff(v0 * 0.70710678118654752f));
                    v1 = 0.5f * v1 * (1.0f + erff(v1 * 0.70710678118654752f));
                }
                if (EPI == 3) {
                    v0 += bias[col]     + res[(size_t)row * N + col];
                    v1 += bias[col + 1] + res[(size_t)row * N + col + 1];
                }
                float2 o = make_float2(v0, v1);
                *(float2*)(Cout + (size_t)row * N + col) = o;
            }
        }
    }
}

// ---------------- depthwise causal conv1d (d_conv=4) + silu, float4 --------
__global__ void conv_silu_k(const float* __restrict__ xz, const float* __restrict__ cw,
                            const float* __restrict__ cb, float* __restrict__ xm) {
    int idx = blockIdx.x * blockDim.x + threadIdx.x;   // MM*DIN/4 threads
    if (idx >= MM * DIN / 4) return;
    int d4 = (idx & 127) << 2;       // channel group base (0..508)
    int t  = idx >> 7;               // token index b*L + l
    int l  = t & (LL - 1);
    int b  = t >> 10;
    float4 acc = *(const float4*)(cb + d4);
    float4 w0 = *(const float4*)(cw + (d4 + 0) * 4);
    float4 w1 = *(const float4*)(cw + (d4 + 1) * 4);
    float4 w2 = *(const float4*)(cw + (d4 + 2) * 4);
    float4 w3 = *(const float4*)(cw + (d4 + 3) * 4);
    const float* wx[4] = {&w0.x, &w1.x, &w2.x, &w3.x};
#pragma unroll
    for (int k = 0; k < 4; k++) {
        int ls = l + k - 3;
        if (ls >= 0) {
            float4 v = *(const float4*)(xz + ((size_t)((b << 10) + ls)) * (2 * DIN) + d4);
            acc.x = fmaf(v.x, wx[0][k], acc.x);
            acc.y = fmaf(v.y, wx[1][k], acc.y);
            acc.z = fmaf(v.z, wx[2][k], acc.z);
            acc.w = fmaf(v.w, wx[3][k], acc.w);
        }
    }
    acc.x = acc.x / (1.0f + __expf(-acc.x));
    acc.y = acc.y / (1.0f + __expf(-acc.y));
    acc.z = acc.z / (1.0f + __expf(-acc.z));
    acc.w = acc.w / (1.0f + __expf(-acc.w));
    *(float4*)(xm + (size_t)t * DIN + d4) = acc;
}

// ---------------- small GEMM: dbl = xm(8192x512) @ W_x(512x48) -------------
__global__ void gemm_wx_k(const float* __restrict__ xm, const float* __restrict__ Wx,
                          float* __restrict__ dbl) {
    __shared__ float As[32][17];
    __shared__ float Ws[16][48];
    int m0  = blockIdx.x * 32;
    int tid = threadIdx.x;           // 256
    int row = tid >> 3;              // 0..31
    int cg  = tid & 7;               // col group, 6 cols each
    float acc[6] = {0.f, 0.f, 0.f, 0.f, 0.f, 0.f};
    for (int kc = 0; kc < DIN; kc += 16) {
        int e = tid * 2;
        As[e >> 4][e & 15]       = xm[(size_t)(m0 + (e >> 4)) * DIN + kc + (e & 15)];
        e++;
        As[e >> 4][e & 15]       = xm[(size_t)(m0 + (e >> 4)) * DIN + kc + (e & 15)];
        int f = tid * 3;
#pragma unroll
        for (int q = 0; q < 3; q++, f++)
            Ws[f / 48][f % 48] = Wx[(size_t)(kc + f / 48) * 48 + (f % 48)];
        __syncthreads();
#pragma unroll
        for (int kk = 0; kk < 16; kk++) {
            float a = As[row][kk];
#pragma unroll
            for (int j = 0; j < 6; j++)
                acc[j] = fmaf(a, Ws[kk][cg * 6 + j], acc[j]);
        }
        __syncthreads();
    }
#pragma unroll
    for (int j = 0; j < 6; j++)
        dbl[(size_t)(m0 + row) * 48 + cg * 6 + j] = acc[j];
}

// -------- dt = softplus(dbl[:, :16] @ W_dt + b_dt), W in registers ---------
__global__ __launch_bounds__(256)
void dt2_k(const float* __restrict__ dbl, const float* __restrict__ Wdt,
           const float* __restrict__ bdt, float* __restrict__ dt) {
    __shared__ float sdt[32][17];
    int m0 = blockIdx.x * 32;
    int tid = threadIdx.x;
#pragma unroll
    for (int q = 0; q < 2; q++) {
        int e = tid + q * 256;
        sdt[e >> 4][e & 15] = dbl[(size_t)(m0 + (e >> 4)) * 48 + (e & 15)];
    }
    int c0 = tid, c1 = tid + 256;
    float w0[16], w1[16];
#pragma unroll
    for (int k = 0; k < 16; k++) {
        w0[k] = Wdt[k * DIN + c0];
        w1[k] = Wdt[k * DIN + c1];
    }
    float b0v = bdt[c0], b1v = bdt[c1];
    __syncthreads();
#pragma unroll 4
    for (int r = 0; r < 32; r++) {
        float a0 = b0v, a1 = b1v;
#pragma unroll
        for (int k = 0; k < 16; k++) {
            float av = sdt[r][k];
            a0 = fmaf(av, w0[k], a0);
            a1 = fmaf(av, w1[k], a1);
        }
        a0 = (a0 > 20.f) ? a0 : log1pf(__expf(a0));
        a1 = (a1 > 20.f) ? a1 : log1pf(__expf(a1));
        dt[(size_t)(m0 + r) * DIN + c0] = a0;
        dt[(size_t)(m0 + r) * DIN + c1] = a1;
    }
}

// ------- selective scan + fused gate: yg = (y + xm*D) * silu(z) ------------
__global__ void scan_k(const float* __restrict__ dt, const float* __restrict__ xm,
                       const float* __restrict__ dbl, const float* __restrict__ Alog,
                       const float* __restrict__ xz, const float* __restrict__ Dp,
                       float* __restrict__ yg) {
    int warpId = threadIdx.x >> 5;
    int lane   = threadIdx.x & 31;
    int gw     = blockIdx.x * (blockDim.x >> 5) + warpId;   // 0..2047
    int b      = gw >> 8;
    int pair   = gw & 255;
    int ch     = lane >> 4;
    int s      = lane & 15;
    int d      = pair * 2 + ch;

    float a  = -__expf(Alog[d * DST + s]);
    float Dv = Dp[d];
    float h  = 0.f;
    int tb = b << 10;
    for (int l = 0; l < LL; l++) {
        int t = tb + l;
        float dtv = dt[(size_t)t * DIN + d];
        float xv  = xm[(size_t)t * DIN + d];
        float Bv  = dbl[(size_t)t * 48 + 16 + s];
        float Cv  = dbl[(size_t)t * 48 + 32 + s];
        float dA  = __expf(dtv * a);
        h = fmaf(dA, h, dtv * xv * Bv);
        float p = h * Cv;
        p += __shfl_xor_sync(0xffffffffu, p, 8);
        p += __shfl_xor_sync(0xffffffffu, p, 4);
        p += __shfl_xor_sync(0xffffffffu, p, 2);
        p += __shfl_xor_sync(0xffffffffu, p, 1);
        if (s == 0) {
            float z  = xz[(size_t)t * (2 * DIN) + DIN + d];
            float sz = z / (1.0f + __expf(-z));
            yg[(size_t)t * DIN + d] = fmaf(xv, Dv, p) * sz;
        }
    }
}

// ---------------------------- launch ---------------------------------------
extern "C" void kernel_launch(void* const* d_in, const int* in_sizes, int n_in,
                              void* d_out, int out_size) {
    const float* x      = (const float*)d_in[0];
    const float* ln1_g  = (const float*)d_in[1];
    const float* ln1_b  = (const float*)d_in[2];
    const float* ln2_g  = (const float*)d_in[3];
    const float* ln2_b  = (const float*)d_in[4];
    const float* W_in   = (const float*)d_in[5];
    const float* conv_w = (const float*)d_in[6];
    const float* conv_b = (const float*)d_in[7];
    const float* W_x    = (const float*)d_in[8];
    const float* W_dt   = (const float*)d_in[9];
    const float* b_dt   = (const float*)d_in[10];
    const float* A_log  = (const float*)d_in[11];
    const float* D_par  = (const float*)d_in[12];
    const float* W_out  = (const float*)d_in[13];
    const float* W1     = (const float*)d_in[14];
    const float* b1     = (const float*)d_in[15];
    const float* W2     = (const float*)d_in[16];
    const float* b2     = (const float*)d_in[17];
    float* out = (float*)d_out;

    float *xt, *xn, *xz, *xm, *dbl, *dtp, *yg, *x2, *xn2, *h1, *x3;
    cudaGetSymbolAddress((void**)&xt,  g_xt);
    cudaGetSymbolAddress((void**)&xn,  g_xn);
    cudaGetSymbolAddress((void**)&xz,  g_xz);
    cudaGetSymbolAddress((void**)&xm,  g_xm);
    cudaGetSymbolAddress((void**)&dbl, g_dbl);
    cudaGetSymbolAddress((void**)&dtp, g_dt);
    cudaGetSymbolAddress((void**)&yg,  g_yg);
    cudaGetSymbolAddress((void**)&x2,  g_x2);
    cudaGetSymbolAddress((void**)&xn2, g_xn2);
    cudaGetSymbolAddress((void**)&h1,  g_h1);
    cudaGetSymbolAddress((void**)&x3,  g_x3);

    // 1) fused transpose + LN1
    trln_k<<<dim3(LL / 32, BB), dim3(32, 8)>>>(x, xt, xn, ln1_g, ln1_b);
    // 2) xz = xn @ W_in
    tf32gemm_k<0><<<dim3((2 * DIN) / 128, MM / 128), 256>>>(xn, W_in, xz, MM, 2 * DIN, CC, nullptr, nullptr);
    // 3) depthwise causal conv + silu (float4)
    conv_silu_k<<<(MM * DIN / 4) / 256, 256>>>(xz, conv_w, conv_b, xm);
    // 4) dbl = xm @ W_x (unchanged from fast R7 config)
    gemm_wx_k<<<MM / 32, 256>>>(xm, W_x, dbl);
    // 5) dt = softplus(dbl[:, :16] @ W_dt + b_dt)
    dt2_k<<<MM / 32, 256>>>(dbl, W_dt, b_dt, dtp);
    // 6) selective scan + fused gate
    scan_k<<<(BB * (DIN / 2)) / 8, 256>>>(dtp, xm, dbl, A_log, xz, D_par, yg);
    // 7) x2 = yg @ W_out + res
    tf32gemm_k<1><<<dim3(CC / 128, MM / 128), 256>>>(yg, W_out, x2, MM, CC, DIN, nullptr, xt);
    // 8) LN2
    layernorm_k<<<MM, 256>>>(x2, xn2, ln2_g, ln2_b);
    // 9) h1 = gelu(xn2 @ W1 + b1)
    tf32gemm_k<2><<<dim3(HID / 128, MM / 128), 256>>>(xn2, W1, h1, MM, HID, CC, b1, nullptr);
    // 10) x3 = h1 @ W2 + b2 + x2
    tf32gemm_k<3><<<dim3(CC / 128, MM / 128), 256>>>(h1, W2, x3, MM, CC, HID, b2, x2);
    // 11) transpose back (B,L,C) -> (B,C,L)
    transpose_k<<<dim3(CC / 32, LL / 32, BB), dim3(32, 8)>>>(x3, out, LL, CC);
}

// round 10
// speedup vs baseline: 1.5005x; 1.5005x over previous
#include <cuda_runtime.h>
#include <math.h>
#include <stdint.h>

// Problem constants
#define BB   8
#define CC   256
#define LL   1024          // H*W
#define DIN  512           // d_inner
#define DST  16            // d_state
#define RANK 16
#define HID  1024
#define MM   (BB*LL)       // 8192 tokens

// ---------------- scratch (device globals; no allocation APIs) -------------
__device__ float g_xt [MM*CC];     // x transposed (B,L,C) == residual 1
__device__ float g_xn [MM*CC];     // LN1 out
__device__ float g_xz [MM*2*DIN];  // xn @ W_in
__device__ float g_xm [MM*DIN];    // conv+silu out
__device__ float g_dbl[MM*48];     // xm @ W_x  (dt_raw | B | C)
__device__ float g_dt [MM*DIN];    // softplus(dt_raw @ W_dt + b_dt)
__device__ float g_y  [MM*DIN];    // scan output
__device__ float g_yg [MM*DIN];    // gated y
__device__ float g_x2 [MM*CC];     // mamba out + res (residual 2)
__device__ float g_xn2[MM*CC];     // LN2 out
__device__ float g_h1 [MM*HID];    // gelu(xn2@W1+b1)
__device__ float g_x3 [MM*CC];     // final (B,L,C) before transpose

// ---------------- batched 2D transpose: (b,R,C) -> (b,C,R) -----------------
__global__ void transpose_k(const float* __restrict__ in, float* __restrict__ out,
                            int R, int Cc) {
    __shared__ float t[32][33];
    int b  = blockIdx.z;
    int r0 = blockIdx.y * 32, c0 = blockIdx.x * 32;
    const float* ib = in  + (size_t)b * R * Cc;
    float*       ob = out + (size_t)b * R * Cc;
#pragma unroll
    for (int i = 0; i < 32; i += 8)
        t[threadIdx.y + i][threadIdx.x] = ib[(r0 + threadIdx.y + i) * Cc + c0 + threadIdx.x];
    __syncthreads();
#pragma unroll
    for (int i = 0; i < 32; i += 8)
        ob[(c0 + threadIdx.y + i) * R + r0 + threadIdx.x] = t[threadIdx.x][threadIdx.y + i];
}

// -------- fused transpose (B,C,L)->(B,L,C) + LayerNorm over C --------------
__global__ __launch_bounds__(256)
void trln_k(const float* __restrict__ in, float* __restrict__ xt,
            float* __restrict__ xn, const float* __restrict__ g,
            const float* __restrict__ bt) {
    __shared__ float t[CC][33];
    __shared__ float ps[8][32], psq[8][32];
    __shared__ float mu[32], rs[32];
    int tx = threadIdx.x, ty = threadIdx.y;   // (32, 8)
    int l0 = blockIdx.x * 32;
    int b  = blockIdx.y;
    const float* ib = in + (size_t)b * CC * LL;

#pragma unroll
    for (int c = ty; c < CC; c += 8)
        t[c][tx] = ib[(size_t)c * LL + l0 + tx];
    __syncthreads();

    float s = 0.f, sq = 0.f;
#pragma unroll
    for (int i = 0; i < 32; i++) {
        float v = t[ty * 32 + i][tx];
        s += v; sq = fmaf(v, v, sq);
    }
    ps[ty][tx] = s; psq[ty][tx] = sq;
    __syncthreads();
    if (ty == 0) {
        float tot = 0.f, totq = 0.f;
#pragma unroll
        for (int i = 0; i < 8; i++) { tot += ps[i][tx]; totq += psq[i][tx]; }
        float m = tot * (1.0f / CC);
        float var = totq * (1.0f / CC) - m * m;
        mu[tx] = m; rs[tx] = rsqrtf(var + 1e-5f);
    }
    __syncthreads();

#pragma unroll
    for (int jj = ty; jj < 32; jj += 8) {
        float m = mu[jj], r = rs[jj];
        size_t base = ((size_t)b * LL + l0 + jj) * CC;
#pragma unroll
        for (int cc = tx; cc < CC; cc += 32) {
            float v = t[cc][jj];
            xt[base + cc] = v;
            xn[base + cc] = (v - m) * r * g[cc] + bt[cc];
        }
    }
}

// ---------------- layernorm over C=256, one block per token (LN2) ----------
__global__ void layernorm_k(const float* __restrict__ in, float* __restrict__ out,
                            const float* __restrict__ g, const float* __restrict__ bt) {
    int row = blockIdx.x;
    int tid = threadIdx.x;          // 256
    float v = in[row * CC + tid];
    float s = v, sq = v * v;
#pragma unroll
    for (int o = 16; o; o >>= 1) {
        s  += __shfl_xor_sync(0xffffffffu, s,  o);
        sq += __shfl_xor_sync(0xffffffffu, sq, o);
    }
    __shared__ float ss[8], ssq[8];
    int w = tid >> 5;
    if ((tid & 31) == 0) { ss[w] = s; ssq[w] = sq; }
    __syncthreads();
    float tot = 0.f, totq = 0.f;
#pragma unroll
    for (int i = 0; i < 8; i++) { tot += ss[i]; totq += ssq[i]; }
    float mu  = tot * (1.0f / CC);
    float var = totq * (1.0f / CC) - mu * mu;
    out[row * CC + tid] = (v - mu) * rsqrtf(var + 1e-5f) * g[tid] + bt[tid];
}

// ---------------- tf32 tensor-core GEMM (R2 version, measured-good) --------
__device__ __forceinline__ uint32_t f2tf32(float x) {
    uint32_t r;
    asm("cvt.rna.tf32.f32 %0, %1;" : "=r"(r) : "f"(x));
    return r;
}

__device__ __forceinline__ void mma_tf32(float* c, const uint32_t* a,
                                         uint32_t b0, uint32_t b1) {
    asm volatile(
        "mma.sync.aligned.m16n8k8.row.col.f32.tf32.tf32.f32 "
        "{%0,%1,%2,%3}, {%4,%5,%6,%7}, {%8,%9}, {%0,%1,%2,%3};"
        : "+f"(c[0]), "+f"(c[1]), "+f"(c[2]), "+f"(c[3])
        : "r"(a[0]), "r"(a[1]), "r"(a[2]), "r"(a[3]), "r"(b0), "r"(b1));
}

template<int EPI>
__global__ __launch_bounds__(256, 2)
void tf32gemm_k(const float* __restrict__ A, const float* __restrict__ Bm,
                float* __restrict__ Cout, int M, int N, int K,
                const float* __restrict__ bias, const float* __restrict__ res) {
    __shared__ uint32_t As[32][132];   // [k][m], padded
    __shared__ uint32_t Bs[32][132];   // [k][n], padded
    int tid  = threadIdx.x;
    int lane = tid & 31, warp = tid >> 5;
    int warpM = warp >> 1, warpN = warp & 1;     // 4 x 2 warps
    int bm = blockIdx.y * 128, bn = blockIdx.x * 128;
    int row4 = lane >> 2, kq = lane & 3;

    float acc[2][8][4];
#pragma unroll
    for (int i = 0; i < 2; i++)
#pragma unroll
        for (int j = 0; j < 8; j++)
#pragma unroll
            for (int q = 0; q < 4; q++) acc[i][j][q] = 0.f;

    for (int k0 = 0; k0 < K; k0 += 32) {
        // load A tile (128 rows x 32 k) -> As[k][m]
#pragma unroll
        for (int q = 0; q < 4; q++) {
            int idx = tid + 256 * q;
            int r = idx >> 3, c = (idx & 7) << 2;
            float4 v = *(const float4*)(A + (size_t)(bm + r) * K + k0 + c);
            As[c + 0][r] = f2tf32(v.x);
            As[c + 1][r] = f2tf32(v.y);
            As[c + 2][r] = f2tf32(v.z);
            As[c + 3][r] = f2tf32(v.w);
        }
        // load B tile (32 k x 128 n) -> Bs[k][n]
#pragma unroll
        for (int q = 0; q < 4; q++) {
            int idx = tid + 256 * q;
            int kk = idx >> 5, n = (idx & 31) << 2;
            float4 v = *(const float4*)(Bm + (size_t)(k0 + kk) * N + bn + n);
            Bs[kk][n + 0] = f2tf32(v.x);
            Bs[kk][n + 1] = f2tf32(v.y);
            Bs[kk][n + 2] = f2tf32(v.z);
            Bs[kk][n + 3] = f2tf32(v.w);
        }
        __syncthreads();
#pragma unroll
        for (int ks = 0; ks < 32; ks += 8) {
            uint32_t af[2][4];
#pragma unroll
            for (int mi = 0; mi < 2; mi++) {
                int m0 = warpM * 32 + mi * 16;
                af[mi][0] = As[ks + kq][m0 + row4];
                af[mi][1] = As[ks + kq][m0 + 8 + row4];
                af[mi][2] = As[ks + 4 + kq][m0 + row4];
                af[mi][3] = As[ks + 4 + kq][m0 + 8 + row4];
            }
#pragma unroll
            for (int ni = 0; ni < 8; ni++) {
                int n0 = warpN * 64 + ni * 8;
                uint32_t b0 = Bs[ks + kq][n0 + row4];
                uint32_t b1 = Bs[ks + 4 + kq][n0 + row4];
                mma_tf32(acc[0][ni], af[0], b0, b1);
                mma_tf32(acc[1][ni], af[1], b0, b1);
            }
        }
        __syncthreads();
    }

    // epilogue
#pragma unroll
    for (int mi = 0; mi < 2; mi++) {
        int r0 = bm + warpM * 32 + mi * 16 + row4;
#pragma unroll
        for (int ni = 0; ni < 8; ni++) {
            int col = bn + warpN * 64 + ni * 8 + kq * 2;
#pragma unroll
            for (int half = 0; half < 2; half++) {
                int row = r0 + half * 8;
                float v0 = acc[mi][ni][half * 2 + 0];
                float v1 = acc[mi][ni][half * 2 + 1];
                if (EPI == 1) {
                    v0 += res[(size_t)row * N + col];
                    v1 += res[(size_t)row * N + col + 1];
                }
                if (EPI == 2) {
                    v0 += bias[col];
                    v1 += bias[col + 1];
                    v0 = 0.5f * v0 * (1.0f + erff(v0 * 0.70710678118654752f));
                    v1 = 0.5f * v1 * (1.0f + erff(v1 * 0.70710678118654752f));
                }
                if (EPI == 3) {
                    v0 += bias[col]     + res[(size_t)row * N + col];
                    v1 += bias[col + 1] + res[(size_t)row * N + col + 1];
                }
                float2 o = make_float2(v0, v1);
                *(float2*)(Cout + (size_t)row * N + col) = o;
            }
        }
    }
}

// ---------------- depthwise causal conv1d (d_conv=4) + silu, float4 --------
__global__ void conv_silu_k(const float* __restrict__ xz, const float* __restrict__ cw,
                            const float* __restrict__ cb, float* __restrict__ xm) {
    int idx = blockIdx.x * blockDim.x + threadIdx.x;   // MM*DIN/4 threads
    if (idx >= MM * DIN / 4) return;
    int d4 = (idx & 127) << 2;       // channel group base (0..508)
    int t  = idx >> 7;               // token index b*L + l
    int l  = t & (LL - 1);
    int b  = t >> 10;
    float4 acc = *(const float4*)(cb + d4);
    float4 w0 = *(const float4*)(cw + (d4 + 0) * 4);
    float4 w1 = *(const float4*)(cw + (d4 + 1) * 4);
    float4 w2 = *(const float4*)(cw + (d4 + 2) * 4);
    float4 w3 = *(const float4*)(cw + (d4 + 3) * 4);
    const float* wx[4] = {&w0.x, &w1.x, &w2.x, &w3.x};
#pragma unroll
    for (int k = 0; k < 4; k++) {
        int ls = l + k - 3;
        if (ls >= 0) {
            float4 v = *(const float4*)(xz + ((size_t)((b << 10) + ls)) * (2 * DIN) + d4);
            acc.x = fmaf(v.x, wx[0][k], acc.x);
            acc.y = fmaf(v.y, wx[1][k], acc.y);
            acc.z = fmaf(v.z, wx[2][k], acc.z);
            acc.w = fmaf(v.w, wx[3][k], acc.w);
        }
    }
    acc.x = acc.x / (1.0f + __expf(-acc.x));
    acc.y = acc.y / (1.0f + __expf(-acc.y));
    acc.z = acc.z / (1.0f + __expf(-acc.z));
    acc.w = acc.w / (1.0f + __expf(-acc.w));
    *(float4*)(xm + (size_t)t * DIN + d4) = acc;
}

// ---------------- small GEMM: dbl = xm(8192x512) @ W_x(512x48) -------------
__global__ void gemm_wx_k(const float* __restrict__ xm, const float* __restrict__ Wx,
                          float* __restrict__ dbl) {
    __shared__ float As[32][17];
    __shared__ float Ws[16][48];
    int m0  = blockIdx.x * 32;
    int tid = threadIdx.x;           // 256
    int row = tid >> 3;              // 0..31
    int cg  = tid & 7;               // col group, 6 cols each
    float acc[6] = {0.f, 0.f, 0.f, 0.f, 0.f, 0.f};
    for (int kc = 0; kc < DIN; kc += 16) {
        int e = tid * 2;
        As[e >> 4][e & 15]       = xm[(size_t)(m0 + (e >> 4)) * DIN + kc + (e & 15)];
        e++;
        As[e >> 4][e & 15]       = xm[(size_t)(m0 + (e >> 4)) * DIN + kc + (e & 15)];
        int f = tid * 3;
#pragma unroll
        for (int q = 0; q < 3; q++, f++)
            Ws[f / 48][f % 48] = Wx[(size_t)(kc + f / 48) * 48 + (f % 48)];
        __syncthreads();
#pragma unroll
        for (int kk = 0; kk < 16; kk++) {
            float a = As[row][kk];
#pragma unroll
            for (int j = 0; j < 6; j++)
                acc[j] = fmaf(a, Ws[kk][cg * 6 + j], acc[j]);
        }
        __syncthreads();
    }
#pragma unroll
    for (int j = 0; j < 6; j++)
        dbl[(size_t)(m0 + row) * 48 + cg * 6 + j] = acc[j];
}

// -------- dt = softplus(dbl[:, :16] @ W_dt + b_dt), W in registers ---------
__global__ __launch_bounds__(256)
void dt2_k(const float* __restrict__ dbl, const float* __restrict__ Wdt,
           const float* __restrict__ bdt, float* __restrict__ dt) {
    __shared__ float sdt[32][17];
    int m0 = blockIdx.x * 32;
    int tid = threadIdx.x;
#pragma unroll
    for (int q = 0; q < 2; q++) {
        int e = tid + q * 256;
        sdt[e >> 4][e & 15] = dbl[(size_t)(m0 + (e >> 4)) * 48 + (e & 15)];
    }
    int c0 = tid, c1 = tid + 256;
    float w0[16], w1[16];
#pragma unroll
    for (int k = 0; k < 16; k++) {
        w0[k] = Wdt[k * DIN + c0];
        w1[k] = Wdt[k * DIN + c1];
    }
    float b0v = bdt[c0], b1v = bdt[c1];
    __syncthreads();
#pragma unroll 4
    for (int r = 0; r < 32; r++) {
        float a0 = b0v, a1 = b1v;
#pragma unroll
        for (int k = 0; k < 16; k++) {
            float av = sdt[r][k];
            a0 = fmaf(av, w0[k], a0);
            a1 = fmaf(av, w1[k], a1);
        }
        a0 = (a0 > 20.f) ? a0 : log1pf(__expf(a0));
        a1 = (a1 > 20.f) ? a1 : log1pf(__expf(a1));
        dt[(size_t)(m0 + r) * DIN + c0] = a0;
        dt[(size_t)(m0 + r) * DIN + c1] = a1;
    }
}

// ---------------- selective scan: half-warp per channel (NO gate) ----------
__global__ void scan_k(const float* __restrict__ dt, const float* __restrict__ xm,
                       const float* __restrict__ dbl, const float* __restrict__ Alog,
                       float* __restrict__ y) {
    int warpId = threadIdx.x >> 5;
    int lane   = threadIdx.x & 31;
    int gw     = blockIdx.x * (blockDim.x >> 5) + warpId;   // 0..2047
    int b      = gw >> 8;                                   // 256 pairs per batch
    int pair   = gw & 255;
    int ch     = lane >> 4;
    int s      = lane & 15;
    int d      = pair * 2 + ch;

    float a = -__expf(Alog[d * DST + s]);
    float h = 0.f;
    int tb = b << 10;
    for (int l = 0; l < LL; l++) {
        int t = tb + l;
        float dtv = dt[(size_t)t * DIN + d];
        float xv  = xm[(size_t)t * DIN + d];
        float Bv  = dbl[(size_t)t * 48 + 16 + s];
        float Cv  = dbl[(size_t)t * 48 + 32 + s];
        float dA  = __expf(dtv * a);
        h = fmaf(dA, h, dtv * xv * Bv);
        float p = h * Cv;
        p += __shfl_xor_sync(0xffffffffu, p, 8);
        p += __shfl_xor_sync(0xffffffffu, p, 4);
        p += __shfl_xor_sync(0xffffffffu, p, 2);
        p += __shfl_xor_sync(0xffffffffu, p, 1);
        if (s == 0) y[(size_t)t * DIN + d] = p;
    }
}

// ---------------- gate: yg = (y + xm*D) * silu(z) --------------------------
__global__ void gate_k(const float* __restrict__ xz, const float* __restrict__ y,
                       const float* __restrict__ xm, const float* __restrict__ Dp,
                       float* __restrict__ yg) {
    int idx = blockIdx.x * blockDim.x + threadIdx.x;
    if (idx >= MM * DIN) return;
    int d = idx & (DIN - 1);
    int t = idx >> 9;
    float z  = xz[(size_t)t * (2 * DIN) + DIN + d];
    float sz = z / (1.0f + __expf(-z));
    yg[idx] = fmaf(xm[idx], Dp[d], y[idx]) * sz;
}

// ---------------------------- launch ---------------------------------------
extern "C" void kernel_launch(void* const* d_in, const int* in_sizes, int n_in,
                              void* d_out, int out_size) {
    const float* x      = (const float*)d_in[0];
    const float* ln1_g  = (const float*)d_in[1];
    const float* ln1_b  = (const float*)d_in[2];
    const float* ln2_g  = (const float*)d_in[3];
    const float* ln2_b  = (const float*)d_in[4];
    const float* W_in   = (const float*)d_in[5];
    const float* conv_w = (const float*)d_in[6];
    const float* conv_b = (const float*)d_in[7];
    const float* W_x    = (const float*)d_in[8];
    const float* W_dt   = (const float*)d_in[9];
    const float* b_dt   = (const float*)d_in[10];
    const float* A_log  = (const float*)d_in[11];
    const float* D_par  = (const float*)d_in[12];
    const float* W_out  = (const float*)d_in[13];
    const float* W1     = (const float*)d_in[14];
    const float* b1     = (const float*)d_in[15];
    const float* W2     = (const float*)d_in[16];
    const float* b2     = (const float*)d_in[17];
    float* out = (float*)d_out;

    float *xt, *xn, *xz, *xm, *dbl, *dtp, *y, *yg, *x2, *xn2, *h1, *x3;
    cudaGetSymbolAddress((void**)&xt,  g_xt);
    cudaGetSymbolAddress((void**)&xn,  g_xn);
    cudaGetSymbolAddress((void**)&xz,  g_xz);
    cudaGetSymbolAddress((void**)&xm,  g_xm);
    cudaGetSymbolAddress((void**)&dbl, g_dbl);
    cudaGetSymbolAddress((void**)&dtp, g_dt);
    cudaGetSymbolAddress((void**)&y,   g_y);
    cudaGetSymbolAddress((void**)&yg,  g_yg);
    cudaGetSymbolAddress((void**)&x2,  g_x2);
    cudaGetSymbolAddress((void**)&xn2, g_xn2);
    cudaGetSymbolAddress((void**)&h1,  g_h1);
    cudaGetSymbolAddress((void**)&x3,  g_x3);

    // 1) fused transpose + LN1  [suspect A under test]
    trln_k<<<dim3(LL / 32, BB), dim3(32, 8)>>>(x, xt, xn, ln1_g, ln1_b);
    // 2) xz = xn @ W_in
    tf32gemm_k<0><<<dim3((2 * DIN) / 128, MM / 128), 256>>>(xn, W_in, xz, MM, 2 * DIN, CC, nullptr, nullptr);
    // 3) depthwise causal conv + silu (float4)  [suspect B under test]
    conv_silu_k<<<(MM * DIN / 4) / 256, 256>>>(xz, conv_w, conv_b, xm);
    // 4) dbl = xm @ W_x
    gemm_wx_k<<<MM / 32, 256>>>(xm, W_x, dbl);
    // 5) dt = softplus(dbl[:, :16] @ W_dt + b_dt)
    dt2_k<<<MM / 32, 256>>>(dbl, W_dt, b_dt, dtp);
    // 6) selective scan (UNfused — suspect C excluded)
    scan_k<<<(BB * (DIN / 2)) / 8, 256>>>(dtp, xm, dbl, A_log, y);
    // 7) gate (separate, as in fast runs)
    gate_k<<<(MM * DIN) / 256, 256>>>(xz, y, xm, D_par, yg);
    // 8) x2 = yg @ W_out + res
    tf32gemm_k<1><<<dim3(CC / 128, MM / 128), 256>>>(yg, W_out, x2, MM, CC, DIN, nullptr, xt);
    // 9) LN2
    layernorm_k<<<MM, 256>>>(x2, xn2, ln2_g, ln2_b);
    // 10) h1 = gelu(xn2 @ W1 + b1)
    tf32gemm_k<2><<<dim3(HID / 128, MM / 128), 256>>>(xn2, W1, h1, MM, HID, CC, b1, nullptr);
    // 11) x3 = h1 @ W2 + b2 + x2
    tf32gemm_k<3><<<dim3(CC / 128, MM / 128), 256>>>(h1, W2, x3, MM, CC, HID, b2, x2);
    // 12) transpose back (B,L,C) -> (B,C,L)
    transpose_k<<<dim3(CC / 32, LL / 32, BB), dim3(32, 8)>>>(x3, out, LL, CC);
}

// round 11
// speedup vs baseline: 1.6680x; 1.1116x over previous
#include <cuda_runtime.h>
#include <math.h>
#include <stdint.h>

// Problem constants
#define BB   8
#define CC   256
#define LL   1024          // H*W
#define DIN  512           // d_inner
#define DST  16            // d_state
#define RANK 16
#define HID  1024
#define MM   (BB*LL)       // 8192 tokens

// ---------------- scratch (device globals; no allocation APIs) -------------
__device__ float g_xt [MM*CC];     // x transposed (B,L,C) == residual 1
__device__ float g_xn [MM*CC];     // LN1 out
__device__ float g_xz [MM*2*DIN];  // xn @ W_in
__device__ float g_xm [MM*DIN];    // conv+silu out
__device__ float g_dbl[MM*48];     // xm @ W_x  (dt_raw | B | C)
__device__ float g_dt [MM*DIN];    // softplus(dt_raw @ W_dt + b_dt)
__device__ float g_y  [MM*DIN];    // scan output
__device__ float g_yg [MM*DIN];    // gated y
__device__ float g_x2 [MM*CC];     // mamba out + res (residual 2)
__device__ float g_xn2[MM*CC];     // LN2 out
__device__ float g_h1 [MM*HID];    // gelu(xn2@W1+b1)
__device__ float g_x3 [MM*CC];     // final (B,L,C) before transpose

// ---------------- batched 2D transpose: (b,R,C) -> (b,C,R) -----------------
__global__ void transpose_k(const float* __restrict__ in, float* __restrict__ out,
                            int R, int Cc) {
    __shared__ float t[32][33];
    int b  = blockIdx.z;
    int r0 = blockIdx.y * 32, c0 = blockIdx.x * 32;
    const float* ib = in  + (size_t)b * R * Cc;
    float*       ob = out + (size_t)b * R * Cc;
#pragma unroll
    for (int i = 0; i < 32; i += 8)
        t[threadIdx.y + i][threadIdx.x] = ib[(r0 + threadIdx.y + i) * Cc + c0 + threadIdx.x];
    __syncthreads();
#pragma unroll
    for (int i = 0; i < 32; i += 8)
        ob[(c0 + threadIdx.y + i) * R + r0 + threadIdx.x] = t[threadIdx.x][threadIdx.y + i];
}

// -------- fused transpose (B,C,L)->(B,L,C) + LayerNorm over C --------------
__global__ __launch_bounds__(256)
void trln_k(const float* __restrict__ in, float* __restrict__ xt,
            float* __restrict__ xn, const float* __restrict__ g,
            const float* __restrict__ bt) {
    __shared__ float t[CC][33];
    __shared__ float ps[8][32], psq[8][32];
    __shared__ float mu[32], rs[32];
    int tx = threadIdx.x, ty = threadIdx.y;   // (32, 8)
    int l0 = blockIdx.x * 32;
    int b  = blockIdx.y;
    const float* ib = in + (size_t)b * CC * LL;

#pragma unroll
    for (int c = ty; c < CC; c += 8)
        t[c][tx] = ib[(size_t)c * LL + l0 + tx];
    __syncthreads();

    float s = 0.f, sq = 0.f;
#pragma unroll
    for (int i = 0; i < 32; i++) {
        float v = t[ty * 32 + i][tx];
        s += v; sq = fmaf(v, v, sq);
    }
    ps[ty][tx] = s; psq[ty][tx] = sq;
    __syncthreads();
    if (ty == 0) {
        float tot = 0.f, totq = 0.f;
#pragma unroll
        for (int i = 0; i < 8; i++) { tot += ps[i][tx]; totq += psq[i][tx]; }
        float m = tot * (1.0f / CC);
        float var = totq * (1.0f / CC) - m * m;
        mu[tx] = m; rs[tx] = rsqrtf(var + 1e-5f);
    }
    __syncthreads();

#pragma unroll
    for (int jj = ty; jj < 32; jj += 8) {
        float m = mu[jj], r = rs[jj];
        size_t base = ((size_t)b * LL + l0 + jj) * CC;
#pragma unroll
        for (int cc = tx; cc < CC; cc += 32) {
            float v = t[cc][jj];
            xt[base + cc] = v;
            xn[base + cc] = (v - m) * r * g[cc] + bt[cc];
        }
    }
}

// ---------------- layernorm over C=256, one block per token (LN2) ----------
__global__ void layernorm_k(const float* __restrict__ in, float* __restrict__ out,
                            const float* __restrict__ g, const float* __restrict__ bt) {
    int row = blockIdx.x;
    int tid = threadIdx.x;          // 256
    float v = in[row * CC + tid];
    float s = v, sq = v * v;
#pragma unroll
    for (int o = 16; o; o >>= 1) {
        s  += __shfl_xor_sync(0xffffffffu, s,  o);
        sq += __shfl_xor_sync(0xffffffffu, sq, o);
    }
    __shared__ float ss[8], ssq[8];
    int w = tid >> 5;
    if ((tid & 31) == 0) { ss[w] = s; ssq[w] = sq; }
    __syncthreads();
    float tot = 0.f, totq = 0.f;
#pragma unroll
    for (int i = 0; i < 8; i++) { tot += ss[i]; totq += ssq[i]; }
    float mu  = tot * (1.0f / CC);
    float var = totq * (1.0f / CC) - mu * mu;
    out[row * CC + tid] = (v - mu) * rsqrtf(var + 1e-5f) * g[tid] + bt[tid];
}

// ---------------- bf16 tensor-core GEMM ------------------------------------
// Same proven structure as the tf32 kernel, but operands packed bf16x2 along k
// and mma.m16n8k16: half the LDS and half the MMA instructions per FLOP.
__device__ __forceinline__ uint32_t pkbf16(float lo, float hi) {
    uint32_t r;
    asm("cvt.rn.bf16x2.f32 %0, %1, %2;" : "=r"(r) : "f"(hi), "f"(lo));
    return r;
}

__device__ __forceinline__ void mma_bf16(float* c, const uint32_t* a,
                                         uint32_t b0, uint32_t b1) {
    asm volatile(
        "mma.sync.aligned.m16n8k16.row.col.f32.bf16.bf16.f32 "
        "{%0,%1,%2,%3}, {%4,%5,%6,%7}, {%8,%9}, {%0,%1,%2,%3};"
        : "+f"(c[0]), "+f"(c[1]), "+f"(c[2]), "+f"(c[3])
        : "r"(a[0]), "r"(a[1]), "r"(a[2]), "r"(a[3]), "r"(b0), "r"(b1));
}

template<int EPI>
__global__ __launch_bounds__(256, 2)
void bf16gemm_k(const float* __restrict__ A, const float* __restrict__ Bm,
                float* __restrict__ Cout, int M, int N, int K,
                const float* __restrict__ bias, const float* __restrict__ res) {
    __shared__ uint32_t As[16][132];   // [k2][m]: bf16x2 packs (k, k+1)
    __shared__ uint32_t Bs[16][132];   // [k2][n]
    int tid  = threadIdx.x;
    int lane = tid & 31, warp = tid >> 5;
    int warpM = warp >> 1, warpN = warp & 1;     // 4 x 2 warps
    int bm = blockIdx.y * 128, bn = blockIdx.x * 128;
    int row4 = lane >> 2, kq = lane & 3;

    float acc[2][8][4];
#pragma unroll
    for (int i = 0; i < 2; i++)
#pragma unroll
        for (int j = 0; j < 8; j++)
#pragma unroll
            for (int q = 0; q < 4; q++) acc[i][j][q] = 0.f;

    for (int k0 = 0; k0 < K; k0 += 32) {
        // load A tile (128 rows x 32 k) -> As[k2][m], packed along k
#pragma unroll
        for (int q = 0; q < 4; q++) {
            int idx = tid + 256 * q;
            int r = idx >> 3, c = (idx & 7) << 2;
            float4 v = *(const float4*)(A + (size_t)(bm + r) * K + k0 + c);
            As[(c >> 1) + 0][r] = pkbf16(v.x, v.y);
            As[(c >> 1) + 1][r] = pkbf16(v.z, v.w);
        }
        // load B tile (32 k x 128 n) -> Bs[k2][n]: each thread packs 2 k-rows
        {
            int k2 = tid >> 4;               // 0..15
            int n8 = (tid & 15) << 3;        // 0..120
            const float* p0 = Bm + (size_t)(k0 + 2 * k2) * N + bn + n8;
            const float* p1 = p0 + N;
            float4 e0 = *(const float4*)(p0);
            float4 e1 = *(const float4*)(p0 + 4);
            float4 o0 = *(const float4*)(p1);
            float4 o1 = *(const float4*)(p1 + 4);
            Bs[k2][n8 + 0] = pkbf16(e0.x, o0.x);
            Bs[k2][n8 + 1] = pkbf16(e0.y, o0.y);
            Bs[k2][n8 + 2] = pkbf16(e0.z, o0.z);
            Bs[k2][n8 + 3] = pkbf16(e0.w, o0.w);
            Bs[k2][n8 + 4] = pkbf16(e1.x, o1.x);
            Bs[k2][n8 + 5] = pkbf16(e1.y, o1.y);
            Bs[k2][n8 + 6] = pkbf16(e1.z, o1.z);
            Bs[k2][n8 + 7] = pkbf16(e1.w, o1.w);
        }
        __syncthreads();
#pragma unroll
        for (int ks2 = 0; ks2 < 2; ks2++) {
            int kb = ks2 * 8;
            uint32_t af[2][4];
#pragma unroll
            for (int mi = 0; mi < 2; mi++) {
                int m0 = warpM * 32 + mi * 16;
                af[mi][0] = As[kb + kq][m0 + row4];
                af[mi][1] = As[kb + kq][m0 + 8 + row4];
                af[mi][2] = As[kb + 4 + kq][m0 + row4];
                af[mi][3] = As[kb + 4 + kq][m0 + 8 + row4];
            }
#pragma unroll
            for (int ni = 0; ni < 8; ni++) {
                int n0 = warpN * 64 + ni * 8;
                uint32_t b0 = Bs[kb + kq][n0 + row4];
                uint32_t b1 = Bs[kb + 4 + kq][n0 + row4];
                mma_bf16(acc[0][ni], af[0], b0, b1);
                mma_bf16(acc[1][ni], af[1], b0, b1);
            }
        }
        __syncthreads();
    }

    // epilogue
#pragma unroll
    for (int mi = 0; mi < 2; mi++) {
        int r0 = bm + warpM * 32 + mi * 16 + row4;
#pragma unroll
        for (int ni = 0; ni < 8; ni++) {
            int col = bn + warpN * 64 + ni * 8 + kq * 2;
#pragma unroll
            for (int half = 0; half < 2; half++) {
                int row = r0 + half * 8;
                float v0 = acc[mi][ni][half * 2 + 0];
                float v1 = acc[mi][ni][half * 2 + 1];
                if (EPI == 1) {
                    v0 += res[(size_t)row * N + col];
                    v1 += res[(size_t)row * N + col + 1];
                }
                if (EPI == 2) {
                    v0 += bias[col];
                    v1 += bias[col + 1];
                    v0 = 0.5f * v0 * (1.0f + erff(v0 * 0.70710678118654752f));
                    v1 = 0.5f * v1 * (1.0f + erff(v1 * 0.70710678118654752f));
                }
                if (EPI == 3) {
                    v0 += bias[col]     + res[(size_t)row * N + col];
                    v1 += bias[col + 1] + res[(size_t)row * N + col + 1];
                }
                float2 o = make_float2(v0, v1);
                *(float2*)(Cout + (size_t)row * N + col) = o;
            }
        }
    }
}

// ---------------- depthwise causal conv1d (d_conv=4) + silu, float4 --------
__global__ void conv_silu_k(const float* __restrict__ xz, const float* __restrict__ cw,
                            const float* __restrict__ cb, float* __restrict__ xm) {
    int idx = blockIdx.x * blockDim.x + threadIdx.x;   // MM*DIN/4 threads
    if (idx >= MM * DIN / 4) return;
    int d4 = (idx & 127) << 2;       // channel group base (0..508)
    int t  = idx >> 7;               // token index b*L + l
    int l  = t & (LL - 1);
    int b  = t >> 10;
    float4 acc = *(const float4*)(cb + d4);
    float4 w0 = *(const float4*)(cw + (d4 + 0) * 4);
    float4 w1 = *(const float4*)(cw + (d4 + 1) * 4);
    float4 w2 = *(const float4*)(cw + (d4 + 2) * 4);
    float4 w3 = *(const float4*)(cw + (d4 + 3) * 4);
    const float* wx[4] = {&w0.x, &w1.x, &w2.x, &w3.x};
#pragma unroll
    for (int k = 0; k < 4; k++) {
        int ls = l + k - 3;
        if (ls >= 0) {
            float4 v = *(const float4*)(xz + ((size_t)((b << 10) + ls)) * (2 * DIN) + d4);
            acc.x = fmaf(v.x, wx[0][k], acc.x);
            acc.y = fmaf(v.y, wx[1][k], acc.y);
            acc.z = fmaf(v.z, wx[2][k], acc.z);
            acc.w = fmaf(v.w, wx[3][k], acc.w);
        }
    }
    acc.x = acc.x / (1.0f + __expf(-acc.x));
    acc.y = acc.y / (1.0f + __expf(-acc.y));
    acc.z = acc.z / (1.0f + __expf(-acc.z));
    acc.w = acc.w / (1.0f + __expf(-acc.w));
    *(float4*)(xm + (size_t)t * DIN + d4) = acc;
}

// ---------------- small GEMM: dbl = xm(8192x512) @ W_x(512x48) -------------
__global__ void gemm_wx_k(const float* __restrict__ xm, const float* __restrict__ Wx,
                          float* __restrict__ dbl) {
    __shared__ float As[32][17];
    __shared__ float Ws[16][48];
    int m0  = blockIdx.x * 32;
    int tid = threadIdx.x;           // 256
    int row = tid >> 3;              // 0..31
    int cg  = tid & 7;               // col group, 6 cols each
    float acc[6] = {0.f, 0.f, 0.f, 0.f, 0.f, 0.f};
    for (int kc = 0; kc < DIN; kc += 16) {
        int e = tid * 2;
        As[e >> 4][e & 15]       = xm[(size_t)(m0 + (e >> 4)) * DIN + kc + (e & 15)];
        e++;
        As[e >> 4][e & 15]       = xm[(size_t)(m0 + (e >> 4)) * DIN + kc + (e & 15)];
        int f = tid * 3;
#pragma unroll
        for (int q = 0; q < 3; q++, f++)
            Ws[f / 48][f % 48] = Wx[(size_t)(kc + f / 48) * 48 + (f % 48)];
        __syncthreads();
#pragma unroll
        for (int kk = 0; kk < 16; kk++) {
            float a = As[row][kk];
#pragma unroll
            for (int j = 0; j < 6; j++)
                acc[j] = fmaf(a, Ws[kk][cg * 6 + j], acc[j]);
        }
        __syncthreads();
    }
#pragma unroll
    for (int j = 0; j < 6; j++)
        dbl[(size_t)(m0 + row) * 48 + cg * 6 + j] = acc[j];
}

// -------- dt = softplus(dbl[:, :16] @ W_dt + b_dt), W in registers ---------
__global__ __launch_bounds__(256)
void dt2_k(const float* __restrict__ dbl, const float* __restrict__ Wdt,
           const float* __restrict__ bdt, float* __restrict__ dt) {
    __shared__ float sdt[32][17];
    int m0 = blockIdx.x * 32;
    int tid = threadIdx.x;
#pragma unroll
    for (int q = 0; q < 2; q++) {
        int e = tid + q * 256;
        sdt[e >> 4][e & 15] = dbl[(size_t)(m0 + (e >> 4)) * 48 + (e & 15)];
    }
    int c0 = tid, c1 = tid + 256;
    float w0[16], w1[16];
#pragma unroll
    for (int k = 0; k < 16; k++) {
        w0[k] = Wdt[k * DIN + c0];
        w1[k] = Wdt[k * DIN + c1];
    }
    float b0v = bdt[c0], b1v = bdt[c1];
    __syncthreads();
#pragma unroll 4
    for (int r = 0; r < 32; r++) {
        float a0 = b0v, a1 = b1v;
#pragma unroll
        for (int k = 0; k < 16; k++) {
            float av = sdt[r][k];
            a0 = fmaf(av, w0[k], a0);
            a1 = fmaf(av, w1[k], a1);
        }
        a0 = (a0 > 20.f) ? a0 : log1pf(__expf(a0));
        a1 = (a1 > 20.f) ? a1 : log1pf(__expf(a1));
        dt[(size_t)(m0 + r) * DIN + c0] = a0;
        dt[(size_t)(m0 + r) * DIN + c1] = a1;
    }
}

// ---------------- selective scan: half-warp per channel (NO gate) ----------
__global__ void scan_k(const float* __restrict__ dt, const float* __restrict__ xm,
                       const float* __restrict__ dbl, const float* __restrict__ Alog,
                       float* __restrict__ y) {
    int warpId = threadIdx.x >> 5;
    int lane   = threadIdx.x & 31;
    int gw     = blockIdx.x * (blockDim.x >> 5) + warpId;   // 0..2047
    int b      = gw >> 8;                                   // 256 pairs per batch
    int pair   = gw & 255;
    int ch     = lane >> 4;
    int s      = lane & 15;
    int d      = pair * 2 + ch;

    float a = -__expf(Alog[d * DST + s]);
    float h = 0.f;
    int tb = b << 10;
    for (int l = 0; l < LL; l++) {
        int t = tb + l;
        float dtv = dt[(size_t)t * DIN + d];
        float xv  = xm[(size_t)t * DIN + d];
        float Bv  = dbl[(size_t)t * 48 + 16 + s];
        float Cv  = dbl[(size_t)t * 48 + 32 + s];
        float dA  = __expf(dtv * a);
        h = fmaf(dA, h, dtv * xv * Bv);
        float p = h * Cv;
        p += __shfl_xor_sync(0xffffffffu, p, 8);
        p += __shfl_xor_sync(0xffffffffu, p, 4);
        p += __shfl_xor_sync(0xffffffffu, p, 2);
        p += __shfl_xor_sync(0xffffffffu, p, 1);
        if (s == 0) y[(size_t)t * DIN + d] = p;
    }
}

// ---------------- gate: yg = (y + xm*D) * silu(z) --------------------------
__global__ void gate_k(const float* __restrict__ xz, const float* __restrict__ y,
                       const float* __restrict__ xm, const float* __restrict__ Dp,
                       float* __restrict__ yg) {
    int idx = blockIdx.x * blockDim.x + threadIdx.x;
    if (idx >= MM * DIN) return;
    int d = idx & (DIN - 1);
    int t = idx >> 9;
    float z  = xz[(size_t)t * (2 * DIN) + DIN + d];
    float sz = z / (1.0f + __expf(-z));
    yg[idx] = fmaf(xm[idx], Dp[d], y[idx]) * sz;
}

// ---------------------------- launch ---------------------------------------
extern "C" void kernel_launch(void* const* d_in, const int* in_sizes, int n_in,
                              void* d_out, int out_size) {
    const float* x      = (const float*)d_in[0];
    const float* ln1_g  = (const float*)d_in[1];
    const float* ln1_b  = (const float*)d_in[2];
    const float* ln2_g  = (const float*)d_in[3];
    const float* ln2_b  = (const float*)d_in[4];
    const float* W_in   = (const float*)d_in[5];
    const float* conv_w = (const float*)d_in[6];
    const float* conv_b = (const float*)d_in[7];
    const float* W_x    = (const float*)d_in[8];
    const float* W_dt   = (const float*)d_in[9];
    const float* b_dt   = (const float*)d_in[10];
    const float* A_log  = (const float*)d_in[11];
    const float* D_par  = (const float*)d_in[12];
    const float* W_out  = (const float*)d_in[13];
    const float* W1     = (const float*)d_in[14];
    const float* b1     = (const float*)d_in[15];
    const float* W2     = (const float*)d_in[16];
    const float* b2     = (const float*)d_in[17];
    float* out = (float*)d_out;

    float *xt, *xn, *xz, *xm, *dbl, *dtp, *y, *yg, *x2, *xn2, *h1, *x3;
    cudaGetSymbolAddress((void**)&xt,  g_xt);
    cudaGetSymbolAddress((void**)&xn,  g_xn);
    cudaGetSymbolAddress((void**)&xz,  g_xz);
    cudaGetSymbolAddress((void**)&xm,  g_xm);
    cudaGetSymbolAddress((void**)&dbl, g_dbl);
    cudaGetSymbolAddress((void**)&dtp, g_dt);
    cudaGetSymbolAddress((void**)&y,   g_y);
    cudaGetSymbolAddress((void**)&yg,  g_yg);
    cudaGetSymbolAddress((void**)&x2,  g_x2);
    cudaGetSymbolAddress((void**)&xn2, g_xn2);
    cudaGetSymbolAddress((void**)&h1,  g_h1);
    cudaGetSymbolAddress((void**)&x3,  g_x3);

    // 1) fused transpose + LN1
    trln_k<<<dim3(LL / 32, BB), dim3(32, 8)>>>(x, xt, xn, ln1_g, ln1_b);
    // 2) xz = xn @ W_in  (bf16 tensor cores)
    bf16gemm_k<0><<<dim3((2 * DIN) / 128, MM / 128), 256>>>(xn, W_in, xz, MM, 2 * DIN, CC, nullptr, nullptr);
    // 3) depthwise causal conv + silu (float4)
    conv_silu_k<<<(MM * DIN / 4) / 256, 256>>>(xz, conv_w, conv_b, xm);
    // 4) dbl = xm @ W_x (fp32 — feeds the sensitive scan inputs)
    gemm_wx_k<<<MM / 32, 256>>>(xm, W_x, dbl);
    // 5) dt = softplus(dbl[:, :16] @ W_dt + b_dt)
    dt2_k<<<MM / 32, 256>>>(dbl, W_dt, b_dt, dtp);
    // 6) selective scan (unfused — fusion measured at +380us, banned)
    scan_k<<<(BB * (DIN / 2)) / 8, 256>>>(dtp, xm, dbl, A_log, y);
    // 7) gate
    gate_k<<<(MM * DIN) / 256, 256>>>(xz, y, xm, D_par, yg);
    // 8) x2 = yg @ W_out + res  (bf16)
    bf16gemm_k<1><<<dim3(CC / 128, MM / 128), 256>>>(yg, W_out, x2, MM, CC, DIN, nullptr, xt);
    // 9) LN2
    layernorm_k<<<MM, 256>>>(x2, xn2, ln2_g, ln2_b);
    // 10) h1 = gelu(xn2 @ W1 + b1)  (bf16)
    bf16gemm_k<2><<<dim3(HID / 128, MM / 128), 256>>>(xn2, W1, h1, MM, HID, CC, b1, nullptr);
    // 11) x3 = h1 @ W2 + b2 + x2  (bf16)
    bf16gemm_k<3><<<dim3(CC / 128, MM / 128), 256>>>(h1, W2, x3, MM, CC, HID, b2, x2);
    // 12) transpose back (B,L,C) -> (B,C,L)
    transpose_k<<<dim3(CC / 32, LL / 32, BB), dim3(32, 8)>>>(x3, out, LL, CC);
}

// round 12
// speedup vs baseline: 2.6457x; 1.5861x over previous
#include <cuda_runtime.h>
#include <math.h>
#include <stdint.h>

// Problem constants
#define BB   8
#define CC   256
#define LL   1024          // H*W
#define DIN  512           // d_inner
#define DST  16            // d_state
#define RANK 16
#define HID  1024
#define MM   (BB*LL)       // 8192 tokens

// ---------------- scratch (device globals; no allocation APIs) -------------
__device__ float g_xt [MM*CC];     // x transposed (B,L,C) == residual 1
__device__ float g_xn [MM*CC];     // LN1 out
__device__ float g_xz [MM*2*DIN];  // xn @ W_in
__device__ float g_xm [MM*DIN];    // conv+silu out
__device__ float g_dbl[MM*48];     // xm @ W_x  (dt_raw | B | C)
__device__ float g_dt [MM*DIN];    // softplus(dt_raw @ W_dt + b_dt)
__device__ float g_y  [MM*DIN];    // scan output
__device__ float g_yg [MM*DIN];    // gated y
__device__ float g_x2 [MM*CC];     // mamba out + res (residual 2)
__device__ float g_xn2[MM*CC];     // LN2 out
__device__ float g_h1 [MM*HID];    // gelu(xn2@W1+b1)
__device__ float g_x3 [MM*CC];     // final (B,L,C) before transpose

// ---------------- batched 2D transpose: (b,R,C) -> (b,C,R) -----------------
__global__ void transpose_k(const float* __restrict__ in, float* __restrict__ out,
                            int R, int Cc) {
    __shared__ float t[32][33];
    int b  = blockIdx.z;
    int r0 = blockIdx.y * 32, c0 = blockIdx.x * 32;
    const float* ib = in  + (size_t)b * R * Cc;
    float*       ob = out + (size_t)b * R * Cc;
#pragma unroll
    for (int i = 0; i < 32; i += 8)
        t[threadIdx.y + i][threadIdx.x] = ib[(r0 + threadIdx.y + i) * Cc + c0 + threadIdx.x];
    __syncthreads();
#pragma unroll
    for (int i = 0; i < 32; i += 8)
        ob[(c0 + threadIdx.y + i) * R + r0 + threadIdx.x] = t[threadIdx.x][threadIdx.y + i];
}

// -------- fused transpose (B,C,L)->(B,L,C) + LayerNorm over C --------------
__global__ __launch_bounds__(256)
void trln_k(const float* __restrict__ in, float* __restrict__ xt,
            float* __restrict__ xn, const float* __restrict__ g,
            const float* __restrict__ bt) {
    __shared__ float t[CC][33];
    __shared__ float ps[8][32], psq[8][32];
    __shared__ float mu[32], rs[32];
    int tx = threadIdx.x, ty = threadIdx.y;   // (32, 8)
    int l0 = blockIdx.x * 32;
    int b  = blockIdx.y;
    const float* ib = in + (size_t)b * CC * LL;

#pragma unroll
    for (int c = ty; c < CC; c += 8)
        t[c][tx] = ib[(size_t)c * LL + l0 + tx];
    __syncthreads();

    float s = 0.f, sq = 0.f;
#pragma unroll
    for (int i = 0; i < 32; i++) {
        float v = t[ty * 32 + i][tx];
        s += v; sq = fmaf(v, v, sq);
    }
    ps[ty][tx] = s; psq[ty][tx] = sq;
    __syncthreads();
    if (ty == 0) {
        float tot = 0.f, totq = 0.f;
#pragma unroll
        for (int i = 0; i < 8; i++) { tot += ps[i][tx]; totq += psq[i][tx]; }
        float m = tot * (1.0f / CC);
        float var = totq * (1.0f / CC) - m * m;
        mu[tx] = m; rs[tx] = rsqrtf(var + 1e-5f);
    }
    __syncthreads();

#pragma unroll
    for (int jj = ty; jj < 32; jj += 8) {
        float m = mu[jj], r = rs[jj];
        size_t base = ((size_t)b * LL + l0 + jj) * CC;
#pragma unroll
        for (int cc = tx; cc < CC; cc += 32) {
            float v = t[cc][jj];
            xt[base + cc] = v;
            xn[base + cc] = (v - m) * r * g[cc] + bt[cc];
        }
    }
}

// ---------------- layernorm over C=256, one block per token (LN2) ----------
__global__ void layernorm_k(const float* __restrict__ in, float* __restrict__ out,
                            const float* __restrict__ g, const float* __restrict__ bt) {
    int row = blockIdx.x;
    int tid = threadIdx.x;          // 256
    float v = in[row * CC + tid];
    float s = v, sq = v * v;
#pragma unroll
    for (int o = 16; o; o >>= 1) {
        s  += __shfl_xor_sync(0xffffffffu, s,  o);
        sq += __shfl_xor_sync(0xffffffffu, sq, o);
    }
    __shared__ float ss[8], ssq[8];
    int w = tid >> 5;
    if ((tid & 31) == 0) { ss[w] = s; ssq[w] = sq; }
    __syncthreads();
    float tot = 0.f, totq = 0.f;
#pragma unroll
    for (int i = 0; i < 8; i++) { tot += ss[i]; totq += ssq[i]; }
    float mu  = tot * (1.0f / CC);
    float var = totq * (1.0f / CC) - mu * mu;
    out[row * CC + tid] = (v - mu) * rsqrtf(var + 1e-5f) * g[tid] + bt[tid];
}

// ---------------- bf16 tensor-core GEMM ------------------------------------
__device__ __forceinline__ uint32_t pkbf16(float lo, float hi) {
    uint32_t r;
    asm("cvt.rn.bf16x2.f32 %0, %1, %2;" : "=r"(r) : "f"(hi), "f"(lo));
    return r;
}

__device__ __forceinline__ void mma_bf16(float* c, const uint32_t* a,
                                         uint32_t b0, uint32_t b1) {
    asm volatile(
        "mma.sync.aligned.m16n8k16.row.col.f32.bf16.bf16.f32 "
        "{%0,%1,%2,%3}, {%4,%5,%6,%7}, {%8,%9}, {%0,%1,%2,%3};"
        : "+f"(c[0]), "+f"(c[1]), "+f"(c[2]), "+f"(c[3])
        : "r"(a[0]), "r"(a[1]), "r"(a[2]), "r"(a[3]), "r"(b0), "r"(b1));
}

template<int EPI>
__global__ __launch_bounds__(256, 2)
void bf16gemm_k(const float* __restrict__ A, const float* __restrict__ Bm,
                float* __restrict__ Cout, int M, int N, int K,
                const float* __restrict__ bias, const float* __restrict__ res) {
    __shared__ uint32_t As[16][132];   // [k2][m]: bf16x2 packs (k, k+1)
    __shared__ uint32_t Bs[16][132];   // [k2][n]
    int tid  = threadIdx.x;
    int lane = tid & 31, warp = tid >> 5;
    int warpM = warp >> 1, warpN = warp & 1;     // 4 x 2 warps
    int bm = blockIdx.y * 128, bn = blockIdx.x * 128;
    int row4 = lane >> 2, kq = lane & 3;

    float acc[2][8][4];
#pragma unroll
    for (int i = 0; i < 2; i++)
#pragma unroll
        for (int j = 0; j < 8; j++)
#pragma unroll
            for (int q = 0; q < 4; q++) acc[i][j][q] = 0.f;

    for (int k0 = 0; k0 < K; k0 += 32) {
#pragma unroll
        for (int q = 0; q < 4; q++) {
            int idx = tid + 256 * q;
            int r = idx >> 3, c = (idx & 7) << 2;
            float4 v = *(const float4*)(A + (size_t)(bm + r) * K + k0 + c);
            As[(c >> 1) + 0][r] = pkbf16(v.x, v.y);
            As[(c >> 1) + 1][r] = pkbf16(v.z, v.w);
        }
        {
            int k2 = tid >> 4;               // 0..15
            int n8 = (tid & 15) << 3;        // 0..120
            const float* p0 = Bm + (size_t)(k0 + 2 * k2) * N + bn + n8;
            const float* p1 = p0 + N;
            float4 e0 = *(const float4*)(p0);
            float4 e1 = *(const float4*)(p0 + 4);
            float4 o0 = *(const float4*)(p1);
            float4 o1 = *(const float4*)(p1 + 4);
            Bs[k2][n8 + 0] = pkbf16(e0.x, o0.x);
            Bs[k2][n8 + 1] = pkbf16(e0.y, o0.y);
            Bs[k2][n8 + 2] = pkbf16(e0.z, o0.z);
            Bs[k2][n8 + 3] = pkbf16(e0.w, o0.w);
            Bs[k2][n8 + 4] = pkbf16(e1.x, o1.x);
            Bs[k2][n8 + 5] = pkbf16(e1.y, o1.y);
            Bs[k2][n8 + 6] = pkbf16(e1.z, o1.z);
            Bs[k2][n8 + 7] = pkbf16(e1.w, o1.w);
        }
        __syncthreads();
#pragma unroll
        for (int ks2 = 0; ks2 < 2; ks2++) {
            int kb = ks2 * 8;
            uint32_t af[2][4];
#pragma unroll
            for (int mi = 0; mi < 2; mi++) {
                int m0 = warpM * 32 + mi * 16;
                af[mi][0] = As[kb + kq][m0 + row4];
                af[mi][1] = As[kb + kq][m0 + 8 + row4];
                af[mi][2] = As[kb + 4 + kq][m0 + row4];
                af[mi][3] = As[kb + 4 + kq][m0 + 8 + row4];
            }
#pragma unroll
            for (int ni = 0; ni < 8; ni++) {
                int n0 = warpN * 64 + ni * 8;
                uint32_t b0 = Bs[kb + kq][n0 + row4];
                uint32_t b1 = Bs[kb + 4 + kq][n0 + row4];
                mma_bf16(acc[0][ni], af[0], b0, b1);
                mma_bf16(acc[1][ni], af[1], b0, b1);
            }
        }
        __syncthreads();
    }

#pragma unroll
    for (int mi = 0; mi < 2; mi++) {
        int r0 = bm + warpM * 32 + mi * 16 + row4;
#pragma unroll
        for (int ni = 0; ni < 8; ni++) {
            int col = bn + warpN * 64 + ni * 8 + kq * 2;
#pragma unroll
            for (int half = 0; half < 2; half++) {
                int row = r0 + half * 8;
                float v0 = acc[mi][ni][half * 2 + 0];
                float v1 = acc[mi][ni][half * 2 + 1];
                if (EPI == 1) {
                    v0 += res[(size_t)row * N + col];
                    v1 += res[(size_t)row * N + col + 1];
                }
                if (EPI == 2) {
                    v0 += bias[col];
                    v1 += bias[col + 1];
                    v0 = 0.5f * v0 * (1.0f + erff(v0 * 0.70710678118654752f));
                    v1 = 0.5f * v1 * (1.0f + erff(v1 * 0.70710678118654752f));
                }
                if (EPI == 3) {
                    v0 += bias[col]     + res[(size_t)row * N + col];
                    v1 += bias[col + 1] + res[(size_t)row * N + col + 1];
                }
                float2 o = make_float2(v0, v1);
                *(float2*)(Cout + (size_t)row * N + col) = o;
            }
        }
    }
}

// ---------------- depthwise causal conv1d (d_conv=4) + silu, float4 --------
__global__ void conv_silu_k(const float* __restrict__ xz, const float* __restrict__ cw,
                            const float* __restrict__ cb, float* __restrict__ xm) {
    int idx = blockIdx.x * blockDim.x + threadIdx.x;   // MM*DIN/4 threads
    if (idx >= MM * DIN / 4) return;
    int d4 = (idx & 127) << 2;       // channel group base (0..508)
    int t  = idx >> 7;               // token index b*L + l
    int l  = t & (LL - 1);
    int b  = t >> 10;
    float4 acc = *(const float4*)(cb + d4);
    float4 w0 = *(const float4*)(cw + (d4 + 0) * 4);
    float4 w1 = *(const float4*)(cw + (d4 + 1) * 4);
    float4 w2 = *(const float4*)(cw + (d4 + 2) * 4);
    float4 w3 = *(const float4*)(cw + (d4 + 3) * 4);
    const float* wx[4] = {&w0.x, &w1.x, &w2.x, &w3.x};
#pragma unroll
    for (int k = 0; k < 4; k++) {
        int ls = l + k - 3;
        if (ls >= 0) {
            float4 v = *(const float4*)(xz + ((size_t)((b << 10) + ls)) * (2 * DIN) + d4);
            acc.x = fmaf(v.x, wx[0][k], acc.x);
            acc.y = fmaf(v.y, wx[1][k], acc.y);
            acc.z = fmaf(v.z, wx[2][k], acc.z);
            acc.w = fmaf(v.w, wx[3][k], acc.w);
        }
    }
    acc.x = acc.x / (1.0f + __expf(-acc.x));
    acc.y = acc.y / (1.0f + __expf(-acc.y));
    acc.z = acc.z / (1.0f + __expf(-acc.z));
    acc.w = acc.w / (1.0f + __expf(-acc.w));
    *(float4*)(xm + (size_t)t * DIN + d4) = acc;
}

// ---------------- small GEMM: dbl = xm(8192x512) @ W_x(512x48) -------------
__global__ void gemm_wx_k(const float* __restrict__ xm, const float* __restrict__ Wx,
                          float* __restrict__ dbl) {
    __shared__ float As[32][17];
    __shared__ float Ws[16][48];
    int m0  = blockIdx.x * 32;
    int tid = threadIdx.x;           // 256
    int row = tid >> 3;              // 0..31
    int cg  = tid & 7;               // col group, 6 cols each
    float acc[6] = {0.f, 0.f, 0.f, 0.f, 0.f, 0.f};
    for (int kc = 0; kc < DIN; kc += 16) {
        int e = tid * 2;
        As[e >> 4][e & 15]       = xm[(size_t)(m0 + (e >> 4)) * DIN + kc + (e & 15)];
        e++;
        As[e >> 4][e & 15]       = xm[(size_t)(m0 + (e >> 4)) * DIN + kc + (e & 15)];
        int f = tid * 3;
#pragma unroll
        for (int q = 0; q < 3; q++, f++)
            Ws[f / 48][f % 48] = Wx[(size_t)(kc + f / 48) * 48 + (f % 48)];
        __syncthreads();
#pragma unroll
        for (int kk = 0; kk < 16; kk++) {
            float a = As[row][kk];
#pragma unroll
            for (int j = 0; j < 6; j++)
                acc[j] = fmaf(a, Ws[kk][cg * 6 + j], acc[j]);
        }
        __syncthreads();
    }
#pragma unroll
    for (int j = 0; j < 6; j++)
        dbl[(size_t)(m0 + row) * 48 + cg * 6 + j] = acc[j];
}

// -------- dt = softplus(dbl[:, :16] @ W_dt + b_dt), W in registers ---------
__global__ __launch_bounds__(256)
void dt2_k(const float* __restrict__ dbl, const float* __restrict__ Wdt,
           const float* __restrict__ bdt, float* __restrict__ dt) {
    __shared__ float sdt[32][17];
    int m0 = blockIdx.x * 32;
    int tid = threadIdx.x;
#pragma unroll
    for (int q = 0; q < 2; q++) {
        int e = tid + q * 256;
        sdt[e >> 4][e & 15] = dbl[(size_t)(m0 + (e >> 4)) * 48 + (e & 15)];
    }
    int c0 = tid, c1 = tid + 256;
    float w0[16], w1[16];
#pragma unroll
    for (int k = 0; k < 16; k++) {
        w0[k] = Wdt[k * DIN + c0];
        w1[k] = Wdt[k * DIN + c1];
    }
    float b0v = bdt[c0], b1v = bdt[c1];
    __syncthreads();
#pragma unroll 4
    for (int r = 0; r < 32; r++) {
        float a0 = b0v, a1 = b1v;
#pragma unroll
        for (int k = 0; k < 16; k++) {
            float av = sdt[r][k];
            a0 = fmaf(av, w0[k], a0);
            a1 = fmaf(av, w1[k], a1);
        }
        a0 = (a0 > 20.f) ? a0 : log1pf(__expf(a0));
        a1 = (a1 > 20.f) ? a1 : log1pf(__expf(a1));
        dt[(size_t)(m0 + r) * DIN + c0] = a0;
        dt[(size_t)(m0 + r) * DIN + c1] = a1;
    }
}

// ------ selective scan v2: smem-chunked, double-buffered (NO gate) ---------
// Block = one batch x 16 channels; 8 warps, each warp owns 2 channels
// (lanes 0-15 -> ch0 states, 16-31 -> ch1 states). Chunks of 64 tokens are
// staged through shared memory so all global latency is overlapped with the
// previous chunk's compute.
__global__ __launch_bounds__(256)
void scan2_k(const float* __restrict__ dt, const float* __restrict__ xm,
             const float* __restrict__ dbl, const float* __restrict__ Alog,
             float* __restrict__ y) {
    __shared__ float sdt[2][64][16], sxm[2][64][16];
    __shared__ float sB[2][64][16], sC[2][64][16];
    __shared__ float sy[64][16];

    int tid  = threadIdx.x;
    int warp = tid >> 5, lane = tid & 31;
    int ch   = lane >> 4, s = lane & 15;
    int wch  = warp * 2 + ch;            // local channel 0..15
    int b    = blockIdx.y;
    int d0   = blockIdx.x * 16;
    int d    = d0 + wch;
    int tb   = b << 10;

    float a = -__expf(Alog[d * DST + s]);
    float h = 0.f;

    int j4 = tid >> 2;                   // token within chunk 0..63
    int i4 = (tid & 3) << 2;             // float4 offset 0,4,8,12

    // preload chunk 0
    {
        size_t t = (size_t)(tb + j4);
        *(float4*)&sdt[0][j4][i4] = *(const float4*)(dt  + t * DIN + d0 + i4);
        *(float4*)&sxm[0][j4][i4] = *(const float4*)(xm  + t * DIN + d0 + i4);
        *(float4*)&sB [0][j4][i4] = *(const float4*)(dbl + t * 48 + 16 + i4);
        *(float4*)&sC [0][j4][i4] = *(const float4*)(dbl + t * 48 + 32 + i4);
    }
    __syncthreads();

    for (int c = 0; c < LL / 64; c++) {
        float4 rd, rx, rb, rc;
        bool more = (c + 1 < LL / 64);
        if (more) {
            size_t t = (size_t)(tb + (c + 1) * 64 + j4);
            rd = *(const float4*)(dt  + t * DIN + d0 + i4);
            rx = *(const float4*)(xm  + t * DIN + d0 + i4);
            rb = *(const float4*)(dbl + t * 48 + 16 + i4);
            rc = *(const float4*)(dbl + t * 48 + 32 + i4);
        }
        int buf = c & 1;
#pragma unroll 4
        for (int j = 0; j < 64; j++) {
            float dtv = sdt[buf][j][wch];
            float xv  = sxm[buf][j][wch];
            float Bv  = sB[buf][j][s];
            float Cv  = sC[buf][j][s];
            float dA  = __expf(dtv * a);
            h = fmaf(dA, h, dtv * xv * Bv);
            float p = h * Cv;
            p += __shfl_xor_sync(0xffffffffu, p, 8);
            p += __shfl_xor_sync(0xffffffffu, p, 4);
            p += __shfl_xor_sync(0xffffffffu, p, 2);
            p += __shfl_xor_sync(0xffffffffu, p, 1);
            if (s == 0) sy[j][wch] = p;
        }
        __syncthreads();
        // coalesced flush of this chunk's outputs
        {
            size_t t = (size_t)(tb + c * 64 + j4);
            *(float4*)(y + t * DIN + d0 + i4) = *(float4*)&sy[j4][i4];
        }
        if (more) {
            int nb = buf ^ 1;
            *(float4*)&sdt[nb][j4][i4] = rd;
            *(float4*)&sxm[nb][j4][i4] = rx;
            *(float4*)&sB [nb][j4][i4] = rb;
            *(float4*)&sC [nb][j4][i4] = rc;
        }
        __syncthreads();
    }
}

// ---------------- gate: yg = (y + xm*D) * silu(z) --------------------------
__global__ void gate_k(const float* __restrict__ xz, const float* __restrict__ y,
                       const float* __restrict__ xm, const float* __restrict__ Dp,
                       float* __restrict__ yg) {
    int idx = blockIdx.x * blockDim.x + threadIdx.x;
    if (idx >= MM * DIN) return;
    int d = idx & (DIN - 1);
    int t = idx >> 9;
    float z  = xz[(size_t)t * (2 * DIN) + DIN + d];
    float sz = z / (1.0f + __expf(-z));
    yg[idx] = fmaf(xm[idx], Dp[d], y[idx]) * sz;
}

// ---------------------------- launch ---------------------------------------
extern "C" void kernel_launch(void* const* d_in, const int* in_sizes, int n_in,
                              void* d_out, int out_size) {
    const float* x      = (const float*)d_in[0];
    const float* ln1_g  = (const float*)d_in[1];
    const float* ln1_b  = (const float*)d_in[2];
    const float* ln2_g  = (const float*)d_in[3];
    const float* ln2_b  = (const float*)d_in[4];
    const float* W_in   = (const float*)d_in[5];
    const float* conv_w = (const float*)d_in[6];
    const float* conv_b = (const float*)d_in[7];
    const float* W_x    = (const float*)d_in[8];
    const float* W_dt   = (const float*)d_in[9];
    const float* b_dt   = (const float*)d_in[10];
    const float* A_log  = (const float*)d_in[11];
    const float* D_par  = (const float*)d_in[12];
    const float* W_out  = (const float*)d_in[13];
    const float* W1     = (const float*)d_in[14];
    const float* b1     = (const float*)d_in[15];
    const float* W2     = (const float*)d_in[16];
    const float* b2     = (const float*)d_in[17];
    float* out = (float*)d_out;

    float *xt, *xn, *xz, *xm, *dbl, *dtp, *y, *yg, *x2, *xn2, *h1, *x3;
    cudaGetSymbolAddress((void**)&xt,  g_xt);
    cudaGetSymbolAddress((void**)&xn,  g_xn);
    cudaGetSymbolAddress((void**)&xz,  g_xz);
    cudaGetSymbolAddress((void**)&xm,  g_xm);
    cudaGetSymbolAddress((void**)&dbl, g_dbl);
    cudaGetSymbolAddress((void**)&dtp, g_dt);
    cudaGetSymbolAddress((void**)&y,   g_y);
    cudaGetSymbolAddress((void**)&yg,  g_yg);
    cudaGetSymbolAddress((void**)&x2,  g_x2);
    cudaGetSymbolAddress((void**)&xn2, g_xn2);
    cudaGetSymbolAddress((void**)&h1,  g_h1);
    cudaGetSymbolAddress((void**)&x3,  g_x3);

    // 1) fused transpose + LN1
    trln_k<<<dim3(LL / 32, BB), dim3(32, 8)>>>(x, xt, xn, ln1_g, ln1_b);
    // 2) xz = xn @ W_in  (bf16 tensor cores)
    bf16gemm_k<0><<<dim3((2 * DIN) / 128, MM / 128), 256>>>(xn, W_in, xz, MM, 2 * DIN, CC, nullptr, nullptr);
    // 3) depthwise causal conv + silu (float4)
    conv_silu_k<<<(MM * DIN / 4) / 256, 256>>>(xz, conv_w, conv_b, xm);
    // 4) dbl = xm @ W_x (fp32)
    gemm_wx_k<<<MM / 32, 256>>>(xm, W_x, dbl);
    // 5) dt = softplus(dbl[:, :16] @ W_dt + b_dt)
    dt2_k<<<MM / 32, 256>>>(dbl, W_dt, b_dt, dtp);
    // 6) selective scan v2 (smem-chunked; gate stays separate)
    scan2_k<<<dim3(DIN / 16, BB), 256>>>(dtp, xm, dbl, A_log, y);
    // 7) gate
    gate_k<<<(MM * DIN) / 256, 256>>>(xz, y, xm, D_par, yg);
    // 8) x2 = yg @ W_out + res  (bf16)
    bf16gemm_k<1><<<dim3(CC / 128, MM / 128), 256>>>(yg, W_out, x2, MM, CC, DIN, nullptr, xt);
    // 9) LN2
    layernorm_k<<<MM, 256>>>(x2, xn2, ln2_g, ln2_b);
    // 10) h1 = gelu(xn2 @ W1 + b1)  (bf16)
    bf16gemm_k<2><<<dim3(HID / 128, MM / 128), 256>>>(xn2, W1, h1, MM, HID, CC, b1, nullptr);
    // 11) x3 = h1 @ W2 + b2 + x2  (bf16)
    bf16gemm_k<3><<<dim3(CC / 128, MM / 128), 256>>>(h1, W2, x3, MM, CC, HID, b2, x2);
    // 12) transpose back (B,L,C) -> (B,C,L)
    transpose_k<<<dim3(CC / 32, LL / 32, BB), dim3(32, 8)>>>(x3, out, LL, CC);
}

// round 13
// speedup vs baseline: 2.7977x; 1.0575x over previous
#include <cuda_runtime.h>
#include <math.h>
#include <stdint.h>

// Problem constants
#define BB   8
#define CC   256
#define LL   1024          // H*W
#define DIN  512           // d_inner
#define DST  16            // d_state
#define RANK 16
#define HID  1024
#define MM   (BB*LL)       // 8192 tokens
#define DBLS 128           // padded dbl row stride

// ---------------- scratch (device globals; no allocation APIs) -------------
__device__ float g_xt [MM*CC];     // x transposed (B,L,C) == residual 1
__device__ float g_xn [MM*CC];     // LN1 out
__device__ float g_xz [MM*2*DIN];  // xn @ W_in
__device__ float g_xm [MM*DIN];    // conv+silu out
__device__ float g_dbl[MM*DBLS];   // xm @ W_x padded (dt_raw | B | C | 0..)
__device__ float g_wxp[DIN*DBLS];  // W_x zero-padded to 512x128
__device__ float g_dt [MM*DIN];    // softplus(dt_raw @ W_dt + b_dt)
__device__ float g_yg [MM*DIN];    // gated scan output
__device__ float g_x2 [MM*CC];     // mamba out + res (residual 2)
__device__ float g_xn2[MM*CC];     // LN2 out
__device__ float g_h1 [MM*HID];    // gelu(xn2@W1+b1)
__device__ float g_x3 [MM*CC];     // final (B,L,C) before transpose

// ---------------- batched 2D transpose: (b,R,C) -> (b,C,R) -----------------
__global__ void transpose_k(const float* __restrict__ in, float* __restrict__ out,
                            int R, int Cc) {
    __shared__ float t[32][33];
    int b  = blockIdx.z;
    int r0 = blockIdx.y * 32, c0 = blockIdx.x * 32;
    const float* ib = in  + (size_t)b * R * Cc;
    float*       ob = out + (size_t)b * R * Cc;
#pragma unroll
    for (int i = 0; i < 32; i += 8)
        t[threadIdx.y + i][threadIdx.x] = ib[(r0 + threadIdx.y + i) * Cc + c0 + threadIdx.x];
    __syncthreads();
#pragma unroll
    for (int i = 0; i < 32; i += 8)
        ob[(c0 + threadIdx.y + i) * R + r0 + threadIdx.x] = t[threadIdx.x][threadIdx.y + i];
}

// -------- fused transpose (B,C,L)->(B,L,C) + LayerNorm over C --------------
__global__ __launch_bounds__(256)
void trln_k(const float* __restrict__ in, float* __restrict__ xt,
            float* __restrict__ xn, const float* __restrict__ g,
            const float* __restrict__ bt) {
    __shared__ float t[CC][33];
    __shared__ float ps[8][32], psq[8][32];
    __shared__ float mu[32], rs[32];
    int tx = threadIdx.x, ty = threadIdx.y;   // (32, 8)
    int l0 = blockIdx.x * 32;
    int b  = blockIdx.y;
    const float* ib = in + (size_t)b * CC * LL;

#pragma unroll
    for (int c = ty; c < CC; c += 8)
        t[c][tx] = ib[(size_t)c * LL + l0 + tx];
    __syncthreads();

    float s = 0.f, sq = 0.f;
#pragma unroll
    for (int i = 0; i < 32; i++) {
        float v = t[ty * 32 + i][tx];
        s += v; sq = fmaf(v, v, sq);
    }
    ps[ty][tx] = s; psq[ty][tx] = sq;
    __syncthreads();
    if (ty == 0) {
        float tot = 0.f, totq = 0.f;
#pragma unroll
        for (int i = 0; i < 8; i++) { tot += ps[i][tx]; totq += psq[i][tx]; }
        float m = tot * (1.0f / CC);
        float var = totq * (1.0f / CC) - m * m;
        mu[tx] = m; rs[tx] = rsqrtf(var + 1e-5f);
    }
    __syncthreads();

#pragma unroll
    for (int jj = ty; jj < 32; jj += 8) {
        float m = mu[jj], r = rs[jj];
        size_t base = ((size_t)b * LL + l0 + jj) * CC;
#pragma unroll
        for (int cc = tx; cc < CC; cc += 32) {
            float v = t[cc][jj];
            xt[base + cc] = v;
            xn[base + cc] = (v - m) * r * g[cc] + bt[cc];
        }
    }
}

// ---------------- layernorm over C=256, one block per token (LN2) ----------
__global__ void layernorm_k(const float* __restrict__ in, float* __restrict__ out,
                            const float* __restrict__ g, const float* __restrict__ bt) {
    int row = blockIdx.x;
    int tid = threadIdx.x;          // 256
    float v = in[row * CC + tid];
    float s = v, sq = v * v;
#pragma unroll
    for (int o = 16; o; o >>= 1) {
        s  += __shfl_xor_sync(0xffffffffu, s,  o);
        sq += __shfl_xor_sync(0xffffffffu, sq, o);
    }
    __shared__ float ss[8], ssq[8];
    int w = tid >> 5;
    if ((tid & 31) == 0) { ss[w] = s; ssq[w] = sq; }
    __syncthreads();
    float tot = 0.f, totq = 0.f;
#pragma unroll
    for (int i = 0; i < 8; i++) { tot += ss[i]; totq += ssq[i]; }
    float mu  = tot * (1.0f / CC);
    float var = totq * (1.0f / CC) - mu * mu;
    out[row * CC + tid] = (v - mu) * rsqrtf(var + 1e-5f) * g[tid] + bt[tid];
}

// ---------------- bf16 tensor-core GEMM ------------------------------------
__device__ __forceinline__ uint32_t pkbf16(float lo, float hi) {
    uint32_t r;
    asm("cvt.rn.bf16x2.f32 %0, %1, %2;" : "=r"(r) : "f"(hi), "f"(lo));
    return r;
}

__device__ __forceinline__ void mma_bf16(float* c, const uint32_t* a,
                                         uint32_t b0, uint32_t b1) {
    asm volatile(
        "mma.sync.aligned.m16n8k16.row.col.f32.bf16.bf16.f32 "
        "{%0,%1,%2,%3}, {%4,%5,%6,%7}, {%8,%9}, {%0,%1,%2,%3};"
        : "+f"(c[0]), "+f"(c[1]), "+f"(c[2]), "+f"(c[3])
        : "r"(a[0]), "r"(a[1]), "r"(a[2]), "r"(a[3]), "r"(b0), "r"(b1));
}

template<int EPI>
__global__ __launch_bounds__(256, 2)
void bf16gemm_k(const float* __restrict__ A, const float* __restrict__ Bm,
                float* __restrict__ Cout, int M, int N, int K,
                const float* __restrict__ bias, const float* __restrict__ res) {
    __shared__ uint32_t As[16][132];   // [k2][m]: bf16x2 packs (k, k+1)
    __shared__ uint32_t Bs[16][132];   // [k2][n]
    int tid  = threadIdx.x;
    int lane = tid & 31, warp = tid >> 5;
    int warpM = warp >> 1, warpN = warp & 1;     // 4 x 2 warps
    int bm = blockIdx.y * 128, bn = blockIdx.x * 128;
    int row4 = lane >> 2, kq = lane & 3;

    float acc[2][8][4];
#pragma unroll
    for (int i = 0; i < 2; i++)
#pragma unroll
        for (int j = 0; j < 8; j++)
#pragma unroll
            for (int q = 0; q < 4; q++) acc[i][j][q] = 0.f;

    for (int k0 = 0; k0 < K; k0 += 32) {
#pragma unroll
        for (int q = 0; q < 4; q++) {
            int idx = tid + 256 * q;
            int r = idx >> 3, c = (idx & 7) << 2;
            float4 v = *(const float4*)(A + (size_t)(bm + r) * K + k0 + c);
            As[(c >> 1) + 0][r] = pkbf16(v.x, v.y);
            As[(c >> 1) + 1][r] = pkbf16(v.z, v.w);
        }
        {
            int k2 = tid >> 4;               // 0..15
            int n8 = (tid & 15) << 3;        // 0..120
            const float* p0 = Bm + (size_t)(k0 + 2 * k2) * N + bn + n8;
            const float* p1 = p0 + N;
            float4 e0 = *(const float4*)(p0);
            float4 e1 = *(const float4*)(p0 + 4);
            float4 o0 = *(const float4*)(p1);
            float4 o1 = *(const float4*)(p1 + 4);
            Bs[k2][n8 + 0] = pkbf16(e0.x, o0.x);
            Bs[k2][n8 + 1] = pkbf16(e0.y, o0.y);
            Bs[k2][n8 + 2] = pkbf16(e0.z, o0.z);
            Bs[k2][n8 + 3] = pkbf16(e0.w, o0.w);
            Bs[k2][n8 + 4] = pkbf16(e1.x, o1.x);
            Bs[k2][n8 + 5] = pkbf16(e1.y, o1.y);
            Bs[k2][n8 + 6] = pkbf16(e1.z, o1.z);
            Bs[k2][n8 + 7] = pkbf16(e1.w, o1.w);
        }
        __syncthreads();
#pragma unroll
        for (int ks2 = 0; ks2 < 2; ks2++) {
            int kb = ks2 * 8;
            uint32_t af[2][4];
#pragma unroll
            for (int mi = 0; mi < 2; mi++) {
                int m0 = warpM * 32 + mi * 16;
                af[mi][0] = As[kb + kq][m0 + row4];
                af[mi][1] = As[kb + kq][m0 + 8 + row4];
                af[mi][2] = As[kb + 4 + kq][m0 + row4];
                af[mi][3] = As[kb + 4 + kq][m0 + 8 + row4];
            }
#pragma unroll
            for (int ni = 0; ni < 8; ni++) {
                int n0 = warpN * 64 + ni * 8;
                uint32_t b0 = Bs[kb + kq][n0 + row4];
                uint32_t b1 = Bs[kb + 4 + kq][n0 + row4];
                mma_bf16(acc[0][ni], af[0], b0, b1);
                mma_bf16(acc[1][ni], af[1], b0, b1);
            }
        }
        __syncthreads();
    }

#pragma unroll
    for (int mi = 0; mi < 2; mi++) {
        int r0 = bm + warpM * 32 + mi * 16 + row4;
#pragma unroll
        for (int ni = 0; ni < 8; ni++) {
            int col = bn + warpN * 64 + ni * 8 + kq * 2;
#pragma unroll
            for (int half = 0; half < 2; half++) {
                int row = r0 + half * 8;
                float v0 = acc[mi][ni][half * 2 + 0];
                float v1 = acc[mi][ni][half * 2 + 1];
                if (EPI == 1) {
                    v0 += res[(size_t)row * N + col];
                    v1 += res[(size_t)row * N + col + 1];
                }
                if (EPI == 2) {
                    v0 += bias[col];
                    v1 += bias[col + 1];
                    v0 = 0.5f * v0 * (1.0f + erff(v0 * 0.70710678118654752f));
                    v1 = 0.5f * v1 * (1.0f + erff(v1 * 0.70710678118654752f));
                }
                if (EPI == 3) {
                    v0 += bias[col]     + res[(size_t)row * N + col];
                    v1 += bias[col + 1] + res[(size_t)row * N + col + 1];
                }
                float2 o = make_float2(v0, v1);
                *(float2*)(Cout + (size_t)row * N + col) = o;
            }
        }
    }
}

// ---------------- pad W_x (512x48) -> (512x128, zero-filled) ---------------
__global__ void pad_wx_k(const float* __restrict__ Wx, float* __restrict__ Wxp) {
    int idx = blockIdx.x * blockDim.x + threadIdx.x;   // DIN*DBLS
    int k = idx >> 7, n = idx & 127;
    Wxp[idx] = (n < 48) ? Wx[k * 48 + n] : 0.0f;
}

// ---------------- depthwise causal conv1d (d_conv=4) + silu, float4 --------
__global__ void conv_silu_k(const float* __restrict__ xz, const float* __restrict__ cw,
                            const float* __restrict__ cb, float* __restrict__ xm) {
    int idx = blockIdx.x * blockDim.x + threadIdx.x;   // MM*DIN/4 threads
    if (idx >= MM * DIN / 4) return;
    int d4 = (idx & 127) << 2;       // channel group base (0..508)
    int t  = idx >> 7;               // token index b*L + l
    int l  = t & (LL - 1);
    int b  = t >> 10;
    float4 acc = *(const float4*)(cb + d4);
    float4 w0 = *(const float4*)(cw + (d4 + 0) * 4);
    float4 w1 = *(const float4*)(cw + (d4 + 1) * 4);
    float4 w2 = *(const float4*)(cw + (d4 + 2) * 4);
    float4 w3 = *(const float4*)(cw + (d4 + 3) * 4);
    const float* wx[4] = {&w0.x, &w1.x, &w2.x, &w3.x};
#pragma unroll
    for (int k = 0; k < 4; k++) {
        int ls = l + k - 3;
        if (ls >= 0) {
            float4 v = *(const float4*)(xz + ((size_t)((b << 10) + ls)) * (2 * DIN) + d4);
            acc.x = fmaf(v.x, wx[0][k], acc.x);
            acc.y = fmaf(v.y, wx[1][k], acc.y);
            acc.z = fmaf(v.z, wx[2][k], acc.z);
            acc.w = fmaf(v.w, wx[3][k], acc.w);
        }
    }
    acc.x = acc.x / (1.0f + __expf(-acc.x));
    acc.y = acc.y / (1.0f + __expf(-acc.y));
    acc.z = acc.z / (1.0f + __expf(-acc.z));
    acc.w = acc.w / (1.0f + __expf(-acc.w));
    *(float4*)(xm + (size_t)t * DIN + d4) = acc;
}

// -------- dt = softplus(dbl[:, :16] @ W_dt + b_dt), W in registers ---------
__global__ __launch_bounds__(256)
void dt2_k(const float* __restrict__ dbl, const float* __restrict__ Wdt,
           const float* __restrict__ bdt, float* __restrict__ dt) {
    __shared__ float sdt[32][17];
    int m0 = blockIdx.x * 32;
    int tid = threadIdx.x;
#pragma unroll
    for (int q = 0; q < 2; q++) {
        int e = tid + q * 256;
        sdt[e >> 4][e & 15] = dbl[(size_t)(m0 + (e >> 4)) * DBLS + (e & 15)];
    }
    int c0 = tid, c1 = tid + 256;
    float w0[16], w1[16];
#pragma unroll
    for (int k = 0; k < 16; k++) {
        w0[k] = Wdt[k * DIN + c0];
        w1[k] = Wdt[k * DIN + c1];
    }
    float b0v = bdt[c0], b1v = bdt[c1];
    __syncthreads();
#pragma unroll 4
    for (int r = 0; r < 32; r++) {
        float a0 = b0v, a1 = b1v;
#pragma unroll
        for (int k = 0; k < 16; k++) {
            float av = sdt[r][k];
            a0 = fmaf(av, w0[k], a0);
            a1 = fmaf(av, w1[k], a1);
        }
        a0 = (a0 > 20.f) ? a0 : log1pf(__expf(a0));
        a1 = (a1 > 20.f) ? a1 : log1pf(__expf(a1));
        dt[(size_t)(m0 + r) * DIN + c0] = a0;
        dt[(size_t)(m0 + r) * DIN + c1] = a1;
    }
}

// ------ selective scan v2 + chunk-level gate (NOT per-iteration) -----------
// Block = one batch x 16 channels; chunks of 64 tokens double-buffered through
// smem. Gate ((y + xm*D) * silu(z)) applies in the coalesced flush stage.
__global__ __launch_bounds__(256)
void scan2_k(const float* __restrict__ dt, const float* __restrict__ xm,
             const float* __restrict__ dbl, const float* __restrict__ Alog,
             const float* __restrict__ xz, const float* __restrict__ Dp,
             float* __restrict__ yg) {
    __shared__ float sdt[2][64][16], sxm[2][64][16];
    __shared__ float sB[2][64][16], sC[2][64][16];
    __shared__ float sz[2][64][16];
    __shared__ float sy[64][16];

    int tid  = threadIdx.x;
    int warp = tid >> 5, lane = tid & 31;
    int ch   = lane >> 4, s = lane & 15;
    int wch  = warp * 2 + ch;            // local channel 0..15
    int b    = blockIdx.y;
    int d0   = blockIdx.x * 16;
    int d    = d0 + wch;
    int tb   = b << 10;

    float a = -__expf(Alog[d * DST + s]);
    float h = 0.f;

    int j4 = tid >> 2;                   // token within chunk 0..63
    int i4 = (tid & 3) << 2;             // float4 offset 0,4,8,12
    float4 Dv = *(const float4*)(Dp + d0 + i4);

    // preload chunk 0
    {
        size_t t = (size_t)(tb + j4);
        *(float4*)&sdt[0][j4][i4] = *(const float4*)(dt  + t * DIN + d0 + i4);
        *(float4*)&sxm[0][j4][i4] = *(const float4*)(xm  + t * DIN + d0 + i4);
        *(float4*)&sB [0][j4][i4] = *(const float4*)(dbl + t * DBLS + 16 + i4);
        *(float4*)&sC [0][j4][i4] = *(const float4*)(dbl + t * DBLS + 32 + i4);
        *(float4*)&sz [0][j4][i4] = *(const float4*)(xz  + t * (2 * DIN) + DIN + d0 + i4);
    }
    __syncthreads();

    for (int c = 0; c < LL / 64; c++) {
        float4 rd, rx, rb, rc, rz;
        bool more = (c + 1 < LL / 64);
        if (more) {
            size_t t = (size_t)(tb + (c + 1) * 64 + j4);
            rd = *(const float4*)(dt  + t * DIN + d0 + i4);
            rx = *(const float4*)(xm  + t * DIN + d0 + i4);
            rb = *(const float4*)(dbl + t * DBLS + 16 + i4);
            rc = *(const float4*)(dbl + t * DBLS + 32 + i4);
            rz = *(const float4*)(xz  + t * (2 * DIN) + DIN + d0 + i4);
        }
        int buf = c & 1;
#pragma unroll 4
        for (int j = 0; j < 64; j++) {
            float dtv = sdt[buf][j][wch];
            float xv  = sxm[buf][j][wch];
            float Bv  = sB[buf][j][s];
            float Cv  = sC[buf][j][s];
            float dA  = __expf(dtv * a);
            h = fmaf(dA, h, dtv * xv * Bv);
            float p = h * Cv;
            p += __shfl_xor_sync(0xffffffffu, p, 8);
            p += __shfl_xor_sync(0xffffffffu, p, 4);
            p += __shfl_xor_sync(0xffffffffu, p, 2);
            p += __shfl_xor_sync(0xffffffffu, p, 1);
            if (s == 0) sy[j][wch] = p;
        }
        __syncthreads();
        // gated coalesced flush of this chunk's outputs
        {
            float4 pv = *(float4*)&sy[j4][i4];
            float4 xv = *(float4*)&sxm[buf][j4][i4];
            float4 zv = *(float4*)&sz[buf][j4][i4];
            float4 o;
            o.x = fmaf(xv.x, Dv.x, pv.x) * (zv.x / (1.0f + __expf(-zv.x)));
            o.y = fmaf(xv.y, Dv.y, pv.y) * (zv.y / (1.0f + __expf(-zv.y)));
            o.z = fmaf(xv.z, Dv.z, pv.z) * (zv.z / (1.0f + __expf(-zv.z)));
            o.w = fmaf(xv.w, Dv.w, pv.w) * (zv.w / (1.0f + __expf(-zv.w)));
            size_t t = (size_t)(tb + c * 64 + j4);
            *(float4*)(yg + t * DIN + d0 + i4) = o;
        }
        if (more) {
            int nb = buf ^ 1;
            *(float4*)&sdt[nb][j4][i4] = rd;
            *(float4*)&sxm[nb][j4][i4] = rx;
            *(float4*)&sB [nb][j4][i4] = rb;
            *(float4*)&sC [nb][j4][i4] = rc;
            *(float4*)&sz [nb][j4][i4] = rz;
        }
        __syncthreads();
    }
}

// ---------------------------- launch ---------------------------------------
extern "C" void kernel_launch(void* const* d_in, const int* in_sizes, int n_in,
                              void* d_out, int out_size) {
    const float* x      = (const float*)d_in[0];
    const float* ln1_g  = (const float*)d_in[1];
    const float* ln1_b  = (const float*)d_in[2];
    const float* ln2_g  = (const float*)d_in[3];
    const float* ln2_b  = (const float*)d_in[4];
    const float* W_in   = (const float*)d_in[5];
    const float* conv_w = (const float*)d_in[6];
    const float* conv_b = (const float*)d_in[7];
    const float* W_x    = (const float*)d_in[8];
    const float* W_dt   = (const float*)d_in[9];
    const float* b_dt   = (const float*)d_in[10];
    const float* A_log  = (const float*)d_in[11];
    const float* D_par  = (const float*)d_in[12];
    const float* W_out  = (const float*)d_in[13];
    const float* W1     = (const float*)d_in[14];
    const float* b1     = (const float*)d_in[15];
    const float* W2     = (const float*)d_in[16];
    const float* b2     = (const float*)d_in[17];
    float* out = (float*)d_out;

    float *xt, *xn, *xz, *xm, *dbl, *wxp, *dtp, *yg, *x2, *xn2, *h1, *x3;
    cudaGetSymbolAddress((void**)&xt,  g_xt);
    cudaGetSymbolAddress((void**)&xn,  g_xn);
    cudaGetSymbolAddress((void**)&xz,  g_xz);
    cudaGetSymbolAddress((void**)&xm,  g_xm);
    cudaGetSymbolAddress((void**)&dbl, g_dbl);
    cudaGetSymbolAddress((void**)&wxp, g_wxp);
    cudaGetSymbolAddress((void**)&dtp, g_dt);
    cudaGetSymbolAddress((void**)&yg,  g_yg);
    cudaGetSymbolAddress((void**)&x2,  g_x2);
    cudaGetSymbolAddress((void**)&xn2, g_xn2);
    cudaGetSymbolAddress((void**)&h1,  g_h1);
    cudaGetSymbolAddress((void**)&x3,  g_x3);

    // 1) fused transpose + LN1
    trln_k<<<dim3(LL / 32, BB), dim3(32, 8)>>>(x, xt, xn, ln1_g, ln1_b);
    // 2) xz = xn @ W_in  (bf16)
    bf16gemm_k<0><<<dim3((2 * DIN) / 128, MM / 128), 256>>>(xn, W_in, xz, MM, 2 * DIN, CC, nullptr, nullptr);
    // 3) depthwise causal conv + silu
    conv_silu_k<<<(MM * DIN / 4) / 256, 256>>>(xz, conv_w, conv_b, xm);
    // 4) pad W_x, then dbl = xm @ W_x (padded, bf16 tensor cores)
    pad_wx_k<<<(DIN * DBLS) / 256, 256>>>(W_x, wxp);
    bf16gemm_k<0><<<dim3(DBLS / 128, MM / 128), 256>>>(xm, wxp, dbl, MM, DBLS, DIN, nullptr, nullptr);
    // 5) dt = softplus(dbl[:, :16] @ W_dt + b_dt)
    dt2_k<<<MM / 32, 256>>>(dbl, W_dt, b_dt, dtp);
    // 6) selective scan v2 + chunk-level gate
    scan2_k<<<dim3(DIN / 16, BB), 256>>>(dtp, xm, dbl, A_log, xz, D_par, yg);
    // 7) x2 = yg @ W_out + res  (bf16)
    bf16gemm_k<1><<<dim3(CC / 128, MM / 128), 256>>>(yg, W_out, x2, MM, CC, DIN, nullptr, xt);
    // 8) LN2
    layernorm_k<<<MM, 256>>>(x2, xn2, ln2_g, ln2_b);
    // 9) h1 = gelu(xn2 @ W1 + b1)  (bf16)
    bf16gemm_k<2><<<dim3(HID / 128, MM / 128), 256>>>(xn2, W1, h1, MM, HID, CC, b1, nullptr);
    // 10) x3 = h1 @ W2 + b2 + x2  (bf16)
    bf16gemm_k<3><<<dim3(CC / 128, MM / 128), 256>>>(h1, W2, x3, MM, CC, HID, b2, x2);
    // 11) transpose back (B,L,C) -> (B,C,L)
    transpose_k<<<dim3(CC / 32, LL / 32, BB), dim3(32, 8)>>>(x3, out, LL, CC);
}